// round 9
// baseline (speedup 1.0000x reference)
#include <cuda_runtime.h>
#include <cstdint>

// ---------------------------------------------------------------------------
// GraphAttentionWithMask: 4-head GAT, N=4096, F=512, D=64, E=128, M=64
//
//  K1 wh_kernel    : Wh = (mask*x) @ W[h];  writes Wh + WhTx (tf32 hi/lo interleaved)
//  K2 f12_kernel   : f1/f2[h][n]; u=exp(f2), w=exp(0.2*f2)
//  K3 adjp_kernel  : adjpx[h][n][2m] = tf32 hi/lo of adj[n][m]·aw[h]
//  K4 flash_kernel : masked attention, factored softmax (validated R7),
//                    BOTH gemms via mma.sync.m16n8k8.tf32 with 3xTF32
//                    (hh + hl + lh), split-KV x2
//  K4b merge_kernel: (o1+o2)/(l1+l2), elu
//  K5 final_kernel : out = leaky(cat(heads) @ Wd + bd)
// ---------------------------------------------------------------------------

#define N_  4096
#define F_  512
#define D_  64
#define H_  4
#define E_  128
#define M_  64
#define HN_ (H_ * N_)
#define SLOPE_ 0.2f

__device__ __forceinline__ float2 tf32split(float a) {
    uint32_t hb;
    asm("cvt.rna.tf32.f32 %0, %1;" : "=r"(hb) : "f"(a));
    float hf = __uint_as_float(hb);
    return make_float2(hf, a - hf);
}

__device__ __forceinline__ void mma_tf32(float* d, const uint32_t* a, const uint32_t* b) {
    asm volatile(
        "mma.sync.aligned.m16n8k8.row.col.f32.tf32.tf32.f32 "
        "{%0,%1,%2,%3}, {%4,%5,%6,%7}, {%8,%9}, {%0,%1,%2,%3};"
        : "+f"(d[0]), "+f"(d[1]), "+f"(d[2]), "+f"(d[3])
        : "r"(a[0]), "r"(a[1]), "r"(a[2]), "r"(a[3]), "r"(b[0]), "r"(b[1]));
}

#define FU(x) __float_as_uint(x)

__device__ float g_Wh   [H_ * N_ * D_];
__device__ float g_WhTx [H_ * D_ * 2 * N_];   // [h][d][2n] interleaved hi/lo
__device__ float g_adjpx[H_ * N_ * 2 * M_];   // [h][n][2m] interleaved hi/lo
__device__ float g_f1   [H_ * N_];
__device__ float g_f2   [H_ * N_];
__device__ float g_u    [H_ * N_];            // exp(f2)
__device__ float g_w    [H_ * N_];            // exp(0.2 f2)
__device__ float g_head [H_ * N_ * D_];
__device__ float g_po   [2 * H_ * N_ * D_];   // split-KV partials
__device__ float g_pl   [2 * H_ * N_];

// ---------------------------------------------------------------------------
// K1: Wh = (mask*x) @ W[h].  Grid (N/64, H), 256 threads, 4x4 reg tile.
// ---------------------------------------------------------------------------
__global__ void wh_kernel(const float* __restrict__ x,
                          const float* __restrict__ mask,
                          const float* __restrict__ W) {
    __shared__ float xT[64][68];
    __shared__ float Ws[64][64];
    const int h  = blockIdx.y;
    const int n0 = blockIdx.x * 64;
    const int tid = threadIdx.x;
    const int ty = tid >> 4, tx = tid & 15;

    float acc[4][4] = {};

    for (int f0 = 0; f0 < F_; f0 += 64) {
        __syncthreads();
        for (int e = tid; e < 64 * 16; e += 256) {
            int r = e >> 4, k4 = (e & 15) * 4;
            float mk = mask[n0 + r];
            float4 xv = *(const float4*)&x[(size_t)(n0 + r) * F_ + f0 + k4];
            xT[k4 + 0][r] = xv.x * mk;
            xT[k4 + 1][r] = xv.y * mk;
            xT[k4 + 2][r] = xv.z * mk;
            xT[k4 + 3][r] = xv.w * mk;
        }
        for (int e = tid; e < 64 * 16; e += 256) {
            int rr = e >> 4, c4 = (e & 15) * 4;
            *(float4*)&Ws[rr][c4] =
                *(const float4*)&W[((size_t)h * F_ + f0 + rr) * D_ + c4];
        }
        __syncthreads();
        #pragma unroll 8
        for (int k = 0; k < 64; k++) {
            float4 a = *(float4*)&xT[k][4 * ty];
            float4 b = *(float4*)&Ws[k][4 * tx];
            acc[0][0] += a.x * b.x; acc[0][1] += a.x * b.y; acc[0][2] += a.x * b.z; acc[0][3] += a.x * b.w;
            acc[1][0] += a.y * b.x; acc[1][1] += a.y * b.y; acc[1][2] += a.y * b.z; acc[1][3] += a.y * b.w;
            acc[2][0] += a.z * b.x; acc[2][1] += a.z * b.y; acc[2][2] += a.z * b.z; acc[2][3] += a.z * b.w;
            acc[3][0] += a.w * b.x; acc[3][1] += a.w * b.y; acc[3][2] += a.w * b.z; acc[3][3] += a.w * b.w;
        }
    }
    #pragma unroll
    for (int i = 0; i < 4; i++)
        #pragma unroll
        for (int j = 0; j < 4; j++)
            g_Wh[((size_t)h * N_ + n0 + 4 * ty + i) * D_ + 4 * tx + j] = acc[i][j];
    // transposed hi/lo interleaved copy for flash PV mma (B operand)
    #pragma unroll
    for (int j = 0; j < 4; j++) {
        float2 s0 = tf32split(acc[0][j]);
        float2 s1 = tf32split(acc[1][j]);
        float2 s2 = tf32split(acc[2][j]);
        float2 s3 = tf32split(acc[3][j]);
        size_t base = ((size_t)h * D_ + 4 * tx + j) * (2 * N_) + 2 * (n0 + 4 * ty);
        *(float4*)&g_WhTx[base]     = make_float4(s0.x, s0.y, s1.x, s1.y);
        *(float4*)&g_WhTx[base + 4] = make_float4(s2.x, s2.y, s3.x, s3.y);
    }
}

// ---------------------------------------------------------------------------
// K2: f1/f2 = Wh @ a1/a2; u = exp(f2), w = exp(0.2 f2).  One warp per (h,n).
// ---------------------------------------------------------------------------
__global__ void f12_kernel(const float* __restrict__ a1,
                           const float* __restrict__ a2) {
    int w = (blockIdx.x * blockDim.x + threadIdx.x) >> 5;
    int lane = threadIdx.x & 31;
    int h = w / N_, n = w % N_;
    const float2 v  = ((const float2*)&g_Wh[((size_t)h * N_ + n) * D_])[lane];
    const float2 w1 = ((const float2*)&a1[h * D_])[lane];
    const float2 w2 = ((const float2*)&a2[h * D_])[lane];
    float s1 = v.x * w1.x + v.y * w1.y;
    float s2 = v.x * w2.x + v.y * w2.y;
    #pragma unroll
    for (int off = 16; off; off >>= 1) {
        s1 += __shfl_xor_sync(0xffffffffu, s1, off);
        s2 += __shfl_xor_sync(0xffffffffu, s2, off);
    }
    if (lane == 0) {
        g_f1[h * N_ + n] = s1;
        g_f2[h * N_ + n] = s2;
        g_u [h * N_ + n] = __expf(s2);
        g_w [h * N_ + n] = __expf(0.2f * s2);
    }
}

// ---------------------------------------------------------------------------
// K3: adjpx[h][n][2m] = tf32 hi/lo of adj[n][m]·aw[h].  One warp per (n,m).
// ---------------------------------------------------------------------------
__global__ void adjp_kernel(const float* __restrict__ adj,
                            const float* __restrict__ aw) {
    __shared__ float aws[H_ * E_];
    int tid = threadIdx.x;
    if (tid < H_ * E_) aws[tid] = aw[tid];
    if (tid + 256 < H_ * E_) aws[tid + 256] = aw[tid + 256];
    __syncthreads();

    int w = (blockIdx.x * blockDim.x + tid) >> 5;   // 0..N*M-1
    int lane = tid & 31;
    int n = w / M_, m = w % M_;
    float4 v = ((const float4*)&adj[(size_t)(n * M_ + m) * E_])[lane];
    float s[H_];
    #pragma unroll
    for (int h = 0; h < H_; h++) {
        const float4 aw4 = ((const float4*)&aws[h * E_])[lane];
        s[h] = v.x * aw4.x + v.y * aw4.y + v.z * aw4.z + v.w * aw4.w;
    }
    #pragma unroll
    for (int off = 16; off; off >>= 1) {
        #pragma unroll
        for (int h = 0; h < H_; h++)
            s[h] += __shfl_xor_sync(0xffffffffu, s[h], off);
    }
    if (lane == 0) {
        #pragma unroll
        for (int h = 0; h < H_; h++) {
            float2 sp = tf32split(s[h]);
            *(float2*)&g_adjpx[((size_t)h * N_ + n) * (2 * M_) + 2 * m] = sp;
        }
    }
}

// ---------------------------------------------------------------------------
// K4: flash attention on tensor cores (3xTF32 mma.sync), factored softmax.
// Grid (N/64, H, 2), 256 threads = 8 warps.
// Warp w: m-band (w&3)*16, n/d-half (w>>2)*32 (4 m16n8 blocks).
// smem tiles [row][2k] interleaved hi/lo, pitch 136 floats.
// ---------------------------------------------------------------------------
#define TP_ 136
#define SM_QTX 0
#define SM_KTX (SM_QTX + 64 * TP_)
#define SM_VTX (SM_KTX + 64 * TP_)
#define SM_PX  (SM_VTX + 64 * TP_)
#define SM_F2  (SM_PX  + 64 * TP_)
#define SM_U   (SM_F2 + 64)
#define SM_W   (SM_U  + 64)
#define SM_T   (SM_W  + 64)
#define SM_R   (SM_T  + 64)
#define SM_L   (SM_R  + 64)
#define SM_FLOATS (SM_L + 64)

__global__ void __launch_bounds__(256) flash_kernel() {
    extern __shared__ float sm[];
    float* QTx = sm + SM_QTX;
    float* KTx = sm + SM_KTX;
    float* VTx = sm + SM_VTX;
    float* Px  = sm + SM_PX;
    float* f2s = sm + SM_F2;
    float* us  = sm + SM_U;
    float* ws  = sm + SM_W;
    float* t_s = sm + SM_T;
    float* r_s = sm + SM_R;
    float* l_a = sm + SM_L;

    const int h  = blockIdx.y;
    const int i0 = blockIdx.x * 64;
    const int sp = blockIdx.z;
    const int tid = threadIdx.x;
    const int w = tid >> 5, lane = tid & 31;
    const int gid = lane >> 2, tig = lane & 3;
    const int mw = (w & 3) * 16, nh = (w >> 2) * 32;
    const int r0 = mw + gid, r1 = r0 + 8;

    // prologue: Q tile (interleaved), per-row consts, zero l
    for (int e = tid; e < 64 * 32; e += 256) {
        int r = e >> 5, c4 = (e & 31) * 4;
        *(float4*)&QTx[r * TP_ + c4] =
            *(const float4*)&g_adjpx[((size_t)h * N_ + i0 + r) * (2 * M_) + c4];
    }
    if (tid < 64) {
        float f1v = g_f1[h * N_ + i0 + tid];
        t_s[tid] = -f1v;
        r_s[tid] = __expf(-0.8f * f1v);
        l_a[tid] = 0.f;
    }
    __syncthreads();

    const float t0 = t_s[r0], t1 = t_s[r1];
    const float rr0 = r_s[r0], rr1 = r_s[r1];

    float oacc[4][4] = {};
    float l0 = 0.f, l1 = 0.f;

    for (int jt = sp * 32; jt < sp * 32 + 32; jt++) {
        const int j0 = jt * 64;
        __syncthreads();   // prev PV (reads Px/VTx) done; KTx overwrite safe
        for (int e = tid; e < 64 * 32; e += 256) {
            int r = e >> 5, c4 = (e & 31) * 4;
            *(float4*)&KTx[r * TP_ + c4] =
                *(const float4*)&g_adjpx[((size_t)h * N_ + j0 + r) * (2 * M_) + c4];
            *(float4*)&VTx[r * TP_ + c4] =
                *(const float4*)&g_WhTx[((size_t)h * D_ + r) * (2 * N_) + 2 * j0 + c4];
        }
        if (tid < 64) {
            f2s[tid] = g_f2[h * N_ + j0 + tid];
            us[tid]  = g_u [h * N_ + j0 + tid];
            ws[tid]  = g_w [h * N_ + j0 + tid];
        }
        __syncthreads();

        // ---- S = Q @ K^T via 3xTF32 mma ----
        float sacc[4][4] = {};
        #pragma unroll
        for (int kk = 0; kk < 8; kk++) {
            const int k0 = kk * 8;
            float2 a0 = *(const float2*)&QTx[r0 * TP_ + 2 * (k0 + tig)];
            float2 a1 = *(const float2*)&QTx[r1 * TP_ + 2 * (k0 + tig)];
            float2 a2 = *(const float2*)&QTx[r0 * TP_ + 2 * (k0 + tig + 4)];
            float2 a3 = *(const float2*)&QTx[r1 * TP_ + 2 * (k0 + tig + 4)];
            uint32_t Ah[4] = {FU(a0.x), FU(a1.x), FU(a2.x), FU(a3.x)};
            uint32_t Al[4] = {FU(a0.y), FU(a1.y), FU(a2.y), FU(a3.y)};
            #pragma unroll
            for (int nb = 0; nb < 4; nb++) {
                const int jc = nh + 8 * nb + gid;
                float2 b0 = *(const float2*)&KTx[jc * TP_ + 2 * (k0 + tig)];
                float2 b1 = *(const float2*)&KTx[jc * TP_ + 2 * (k0 + tig + 4)];
                uint32_t Bh[2] = {FU(b0.x), FU(b1.x)};
                uint32_t Bl[2] = {FU(b0.y), FU(b1.y)};
                mma_tf32(sacc[nb], Ah, Bh);
                mma_tf32(sacc[nb], Ah, Bl);
                mma_tf32(sacc[nb], Al, Bh);
            }
        }

        // ---- factored softmax weights + P (hi/lo) to smem ----
        #pragma unroll
        for (int nb = 0; nb < 4; nb++) {
            const int cj = nh + 8 * nb + 2 * tig;
            float f2a = f2s[cj], f2b = f2s[cj + 1];
            float ua = us[cj], ub = us[cj + 1];
            float wa = ws[cj], wb = ws[cj + 1];
            float p00 = (sacc[nb][0] > 0.f) ? ((f2a > t0) ? ua : rr0 * wa) : 0.f;
            float p01 = (sacc[nb][1] > 0.f) ? ((f2b > t0) ? ub : rr0 * wb) : 0.f;
            float p10 = (sacc[nb][2] > 0.f) ? ((f2a > t1) ? ua : rr1 * wa) : 0.f;
            float p11 = (sacc[nb][3] > 0.f) ? ((f2b > t1) ? ub : rr1 * wb) : 0.f;
            l0 += p00 + p01;
            l1 += p10 + p11;
            float2 q00 = tf32split(p00), q01 = tf32split(p01);
            float2 q10 = tf32split(p10), q11 = tf32split(p11);
            *(float4*)&Px[r0 * TP_ + 2 * cj] = make_float4(q00.x, q00.y, q01.x, q01.y);
            *(float4*)&Px[r1 * TP_ + 2 * cj] = make_float4(q10.x, q10.y, q11.x, q11.y);
        }
        __syncthreads();

        // ---- O += P @ V via 3xTF32 mma ----
        #pragma unroll
        for (int kk = 0; kk < 8; kk++) {
            const int k0 = kk * 8;
            float2 a0 = *(const float2*)&Px[r0 * TP_ + 2 * (k0 + tig)];
            float2 a1 = *(const float2*)&Px[r1 * TP_ + 2 * (k0 + tig)];
            float2 a2 = *(const float2*)&Px[r0 * TP_ + 2 * (k0 + tig + 4)];
            float2 a3 = *(const float2*)&Px[r1 * TP_ + 2 * (k0 + tig + 4)];
            uint32_t Ah[4] = {FU(a0.x), FU(a1.x), FU(a2.x), FU(a3.x)};
            uint32_t Al[4] = {FU(a0.y), FU(a1.y), FU(a2.y), FU(a3.y)};
            #pragma unroll
            for (int nb = 0; nb < 4; nb++) {
                const int dc = nh + 8 * nb + gid;
                float2 b0 = *(const float2*)&VTx[dc * TP_ + 2 * (k0 + tig)];
                float2 b1 = *(const float2*)&VTx[dc * TP_ + 2 * (k0 + tig + 4)];
                uint32_t Bh[2] = {FU(b0.x), FU(b1.x)};
                uint32_t Bl[2] = {FU(b0.y), FU(b1.y)};
                mma_tf32(oacc[nb], Ah, Bh);
                mma_tf32(oacc[nb], Ah, Bl);
                mma_tf32(oacc[nb], Al, Bh);
            }
        }
    }

    // l: reduce within quad (lanes sharing rows), combine across warps in smem
    l0 += __shfl_xor_sync(0xffffffffu, l0, 1);
    l0 += __shfl_xor_sync(0xffffffffu, l0, 2);
    l1 += __shfl_xor_sync(0xffffffffu, l1, 1);
    l1 += __shfl_xor_sync(0xffffffffu, l1, 2);
    if (tig == 0) {
        atomicAdd(&l_a[r0], l0);
        atomicAdd(&l_a[r1], l1);
    }
    __syncthreads();

    const int rowb = (sp * H_ + h) * N_ + i0;
    if (tid < 64) g_pl[rowb + tid] = l_a[tid];

    #pragma unroll
    for (int nb = 0; nb < 4; nb++) {
        const int dc = nh + 8 * nb + 2 * tig;
        *(float2*)&g_po[(size_t)(rowb + r0) * D_ + dc] = make_float2(oacc[nb][0], oacc[nb][1]);
        *(float2*)&g_po[(size_t)(rowb + r1) * D_ + dc] = make_float2(oacc[nb][2], oacc[nb][3]);
    }
}

// ---------------------------------------------------------------------------
// K4b: merge the two KV splits, normalize, elu.  One thread per (h,n,d4).
// ---------------------------------------------------------------------------
__global__ void merge_kernel() {
    int idx = blockIdx.x * 256 + threadIdx.x;     // < H*N*16
    int d4 = (idx & 15) * 4;
    int hn = idx >> 4;
    float inv = 1.f / (g_pl[hn] + g_pl[HN_ + hn]);
    float4 o1 = *(const float4*)&g_po[(size_t)hn * D_ + d4];
    float4 o2 = *(const float4*)&g_po[(size_t)(HN_ + hn) * D_ + d4];
    float4 v;
    v.x = (o1.x + o2.x) * inv;
    v.y = (o1.y + o2.y) * inv;
    v.z = (o1.z + o2.z) * inv;
    v.w = (o1.w + o2.w) * inv;
    v.x = (v.x > 0.f) ? v.x : (__expf(v.x) - 1.f);
    v.y = (v.y > 0.f) ? v.y : (__expf(v.y) - 1.f);
    v.z = (v.z > 0.f) ? v.z : (__expf(v.z) - 1.f);
    v.w = (v.w > 0.f) ? v.w : (__expf(v.w) - 1.f);
    *(float4*)&g_head[(size_t)hn * D_ + d4] = v;
}

// ---------------------------------------------------------------------------
// K5: out = leaky( cat(heads) @ Wd + bd ).  Grid N/64, 256 threads.
// ---------------------------------------------------------------------------
__global__ void final_kernel(const float* __restrict__ Wd,
                             const float* __restrict__ bd,
                             float* __restrict__ out) {
    __shared__ float AT[64][68];
    __shared__ float Ws[64][64];
    const int n0 = blockIdx.x * 64;
    const int tid = threadIdx.x;
    const int ty = tid >> 4, tx = tid & 15;

    float acc[4][4] = {};

    for (int h = 0; h < H_; h++) {
        __syncthreads();
        for (int e = tid; e < 64 * 16; e += 256) {
            int r = e >> 4, k4 = (e & 15) * 4;
            float4 a = *(const float4*)&g_head[((size_t)h * N_ + n0 + r) * D_ + k4];
            AT[k4 + 0][r] = a.x;
            AT[k4 + 1][r] = a.y;
            AT[k4 + 2][r] = a.z;
            AT[k4 + 3][r] = a.w;
        }
        for (int e = tid; e < 64 * 16; e += 256) {
            int rr = e >> 4, c4 = (e & 15) * 4;
            *(float4*)&Ws[rr][c4] = *(const float4*)&Wd[(size_t)(h * 64 + rr) * D_ + c4];
        }
        __syncthreads();
        #pragma unroll 8
        for (int k = 0; k < 64; k++) {
            float4 a = *(float4*)&AT[k][4 * ty];
            float4 b = *(float4*)&Ws[k][4 * tx];
            acc[0][0] += a.x * b.x; acc[0][1] += a.x * b.y; acc[0][2] += a.x * b.z; acc[0][3] += a.x * b.w;
            acc[1][0] += a.y * b.x; acc[1][1] += a.y * b.y; acc[1][2] += a.y * b.z; acc[1][3] += a.y * b.w;
            acc[2][0] += a.z * b.x; acc[2][1] += a.z * b.y; acc[2][2] += a.z * b.z; acc[2][3] += a.z * b.w;
            acc[3][0] += a.w * b.x; acc[3][1] += a.w * b.y; acc[3][2] += a.w * b.z; acc[3][3] += a.w * b.w;
        }
    }
    #pragma unroll
    for (int j = 0; j < 4; j++) {
        float b = bd[4 * tx + j];
        #pragma unroll
        for (int i = 0; i < 4; i++) {
            float v = acc[i][j] + b;
            v = (v > 0.f) ? v : SLOPE_ * v;
            out[(size_t)(n0 + 4 * ty + i) * D_ + 4 * tx + j] = v;
        }
    }
}

// ---------------------------------------------------------------------------
extern "C" void kernel_launch(void* const* d_in, const int* in_sizes, int n_in,
                              void* d_out, int out_size) {
    const float* x    = (const float*)d_in[0];
    const float* mask = (const float*)d_in[1];
    const float* adj  = (const float*)d_in[2];
    const float* W    = (const float*)d_in[3];
    const float* a1   = (const float*)d_in[4];
    const float* a2   = (const float*)d_in[5];
    const float* aw   = (const float*)d_in[6];
    const float* Wd   = (const float*)d_in[7];
    const float* bd   = (const float*)d_in[8];
    float* out        = (float*)d_out;

    cudaFuncSetAttribute(flash_kernel,
                         cudaFuncAttributeMaxDynamicSharedMemorySize,
                         SM_FLOATS * (int)sizeof(float));

    wh_kernel<<<dim3(N_ / 64, H_), 256>>>(x, mask, W);
    f12_kernel<<<(H_ * N_) / 8, 256>>>(a1, a2);
    adjp_kernel<<<(N_ * M_) / 8, 256>>>(adj, aw);
    flash_kernel<<<dim3(N_ / 64, H_, 2), 256, SM_FLOATS * (int)sizeof(float)>>>();
    merge_kernel<<<(HN_ * 16) / 256, 256>>>();
    final_kernel<<<N_ / 64, 256>>>(Wd, bd, out);
}

// round 10
// speedup vs baseline: 1.2226x; 1.2226x over previous
#include <cuda_runtime.h>
#include <cstdint>

// ---------------------------------------------------------------------------
// GraphAttentionWithMask: 4-head GAT, N=4096, F=512, D=64, E=128, M=64
//
//  K1 wh_kernel    : Wh = (mask*x) @ W[h];  writes Wh + WhTx (tf32 hi/lo interleaved)
//  K2 f12_kernel   : f1/f2[h][n]; u=exp(f2), w=exp(0.2*f2)
//  K3 adjp_kernel  : adjpx[h][n][2m] = tf32 hi/lo of adj[n][m]·aw[h]
//  K4 flash_kernel : masked attention, factored softmax, 3xTF32 mma.sync,
//                    Q fragments in registers, cp.async double-buffered K/V,
//                    split-KV x2
//  K4b merge_kernel: (o1+o2)/(l1+l2), elu
//  K5 final_kernel : out = leaky(cat(heads) @ Wd + bd)
// ---------------------------------------------------------------------------

#define N_  4096
#define F_  512
#define D_  64
#define H_  4
#define E_  128
#define M_  64
#define HN_ (H_ * N_)
#define SLOPE_ 0.2f

__device__ __forceinline__ float2 tf32split(float a) {
    uint32_t hb;
    asm("cvt.rna.tf32.f32 %0, %1;" : "=r"(hb) : "f"(a));
    float hf = __uint_as_float(hb);
    return make_float2(hf, a - hf);
}

__device__ __forceinline__ void mma_tf32(float* d, const uint32_t* a, const uint32_t* b) {
    asm volatile(
        "mma.sync.aligned.m16n8k8.row.col.f32.tf32.tf32.f32 "
        "{%0,%1,%2,%3}, {%4,%5,%6,%7}, {%8,%9}, {%0,%1,%2,%3};"
        : "+f"(d[0]), "+f"(d[1]), "+f"(d[2]), "+f"(d[3])
        : "r"(a[0]), "r"(a[1]), "r"(a[2]), "r"(a[3]), "r"(b[0]), "r"(b[1]));
}

#define FU(x) __float_as_uint(x)

#define CP_ASYNC16(smaddr, gptr) \
    asm volatile("cp.async.cg.shared.global [%0], [%1], 16;" \
                 :: "r"(smaddr), "l"(gptr))
#define CP_COMMIT() asm volatile("cp.async.commit_group;")
#define CP_WAIT0()  asm volatile("cp.async.wait_group 0;")

__device__ float g_Wh   [H_ * N_ * D_];
__device__ float g_WhTx [H_ * D_ * 2 * N_];   // [h][d][2n] interleaved hi/lo
__device__ float g_adjpx[H_ * N_ * 2 * M_];   // [h][n][2m] interleaved hi/lo
__device__ float g_f1   [H_ * N_];
__device__ float g_f2   [H_ * N_];
__device__ float g_u    [H_ * N_];            // exp(f2)
__device__ float g_w    [H_ * N_];            // exp(0.2 f2)
__device__ float g_head [H_ * N_ * D_];
__device__ float g_po   [2 * H_ * N_ * D_];   // split-KV partials
__device__ float g_pl   [2 * H_ * N_];

// ---------------------------------------------------------------------------
// K1: Wh = (mask*x) @ W[h].  Grid (N/64, H), 256 threads, 4x4 reg tile.
// ---------------------------------------------------------------------------
__global__ void wh_kernel(const float* __restrict__ x,
                          const float* __restrict__ mask,
                          const float* __restrict__ W) {
    __shared__ float xT[64][68];
    __shared__ float Ws[64][64];
    const int h  = blockIdx.y;
    const int n0 = blockIdx.x * 64;
    const int tid = threadIdx.x;
    const int ty = tid >> 4, tx = tid & 15;

    float acc[4][4] = {};

    for (int f0 = 0; f0 < F_; f0 += 64) {
        __syncthreads();
        for (int e = tid; e < 64 * 16; e += 256) {
            int r = e >> 4, k4 = (e & 15) * 4;
            float mk = mask[n0 + r];
            float4 xv = *(const float4*)&x[(size_t)(n0 + r) * F_ + f0 + k4];
            xT[k4 + 0][r] = xv.x * mk;
            xT[k4 + 1][r] = xv.y * mk;
            xT[k4 + 2][r] = xv.z * mk;
            xT[k4 + 3][r] = xv.w * mk;
        }
        for (int e = tid; e < 64 * 16; e += 256) {
            int rr = e >> 4, c4 = (e & 15) * 4;
            *(float4*)&Ws[rr][c4] =
                *(const float4*)&W[((size_t)h * F_ + f0 + rr) * D_ + c4];
        }
        __syncthreads();
        #pragma unroll 8
        for (int k = 0; k < 64; k++) {
            float4 a = *(float4*)&xT[k][4 * ty];
            float4 b = *(float4*)&Ws[k][4 * tx];
            acc[0][0] += a.x * b.x; acc[0][1] += a.x * b.y; acc[0][2] += a.x * b.z; acc[0][3] += a.x * b.w;
            acc[1][0] += a.y * b.x; acc[1][1] += a.y * b.y; acc[1][2] += a.y * b.z; acc[1][3] += a.y * b.w;
            acc[2][0] += a.z * b.x; acc[2][1] += a.z * b.y; acc[2][2] += a.z * b.z; acc[2][3] += a.z * b.w;
            acc[3][0] += a.w * b.x; acc[3][1] += a.w * b.y; acc[3][2] += a.w * b.z; acc[3][3] += a.w * b.w;
        }
    }
    #pragma unroll
    for (int i = 0; i < 4; i++)
        #pragma unroll
        for (int j = 0; j < 4; j++)
            g_Wh[((size_t)h * N_ + n0 + 4 * ty + i) * D_ + 4 * tx + j] = acc[i][j];
    // transposed hi/lo interleaved copy for flash PV mma (B operand)
    #pragma unroll
    for (int j = 0; j < 4; j++) {
        float2 s0 = tf32split(acc[0][j]);
        float2 s1 = tf32split(acc[1][j]);
        float2 s2 = tf32split(acc[2][j]);
        float2 s3 = tf32split(acc[3][j]);
        size_t base = ((size_t)h * D_ + 4 * tx + j) * (2 * N_) + 2 * (n0 + 4 * ty);
        *(float4*)&g_WhTx[base]     = make_float4(s0.x, s0.y, s1.x, s1.y);
        *(float4*)&g_WhTx[base + 4] = make_float4(s2.x, s2.y, s3.x, s3.y);
    }
}

// ---------------------------------------------------------------------------
// K2: f1/f2 = Wh @ a1/a2; u = exp(f2), w = exp(0.2 f2).  One warp per (h,n).
// ---------------------------------------------------------------------------
__global__ void f12_kernel(const float* __restrict__ a1,
                           const float* __restrict__ a2) {
    int w = (blockIdx.x * blockDim.x + threadIdx.x) >> 5;
    int lane = threadIdx.x & 31;
    int h = w / N_, n = w % N_;
    const float2 v  = ((const float2*)&g_Wh[((size_t)h * N_ + n) * D_])[lane];
    const float2 w1 = ((const float2*)&a1[h * D_])[lane];
    const float2 w2 = ((const float2*)&a2[h * D_])[lane];
    float s1 = v.x * w1.x + v.y * w1.y;
    float s2 = v.x * w2.x + v.y * w2.y;
    #pragma unroll
    for (int off = 16; off; off >>= 1) {
        s1 += __shfl_xor_sync(0xffffffffu, s1, off);
        s2 += __shfl_xor_sync(0xffffffffu, s2, off);
    }
    if (lane == 0) {
        g_f1[h * N_ + n] = s1;
        g_f2[h * N_ + n] = s2;
        g_u [h * N_ + n] = __expf(s2);
        g_w [h * N_ + n] = __expf(0.2f * s2);
    }
}

// ---------------------------------------------------------------------------
// K3: adjpx[h][n][2m] = tf32 hi/lo of adj[n][m]·aw[h].  One warp per (n,m).
// ---------------------------------------------------------------------------
__global__ void adjp_kernel(const float* __restrict__ adj,
                            const float* __restrict__ aw) {
    __shared__ float aws[H_ * E_];
    int tid = threadIdx.x;
    if (tid < H_ * E_) aws[tid] = aw[tid];
    if (tid + 256 < H_ * E_) aws[tid + 256] = aw[tid + 256];
    __syncthreads();

    int w = (blockIdx.x * blockDim.x + tid) >> 5;   // 0..N*M-1
    int lane = tid & 31;
    int n = w / M_, m = w % M_;
    float4 v = ((const float4*)&adj[(size_t)(n * M_ + m) * E_])[lane];
    float s[H_];
    #pragma unroll
    for (int h = 0; h < H_; h++) {
        const float4 aw4 = ((const float4*)&aws[h * E_])[lane];
        s[h] = v.x * aw4.x + v.y * aw4.y + v.z * aw4.z + v.w * aw4.w;
    }
    #pragma unroll
    for (int off = 16; off; off >>= 1) {
        #pragma unroll
        for (int h = 0; h < H_; h++)
            s[h] += __shfl_xor_sync(0xffffffffu, s[h], off);
    }
    if (lane == 0) {
        #pragma unroll
        for (int h = 0; h < H_; h++) {
            float2 sp = tf32split(s[h]);
            *(float2*)&g_adjpx[((size_t)h * N_ + n) * (2 * M_) + 2 * m] = sp;
        }
    }
}

// ---------------------------------------------------------------------------
// K4: flash attention, 3xTF32 mma, Q in registers, cp.async double buffer.
// Grid (N/64, H, 2), 256 threads = 8 warps.
// Warp w: m-band (w&3)*16, n/d-half (w>>2)*32.
// smem (floats): KTx[2], VTx[2] (pitch 136), Px, scal[2]{f2,u,w}, T, R, L
// ---------------------------------------------------------------------------
#define TP_ 136
#define SM_KTX(b) ((b) * 64 * TP_)
#define SM_VTX(b) ((2 + (b)) * 64 * TP_)
#define SM_PX     (4 * 64 * TP_)
#define SM_SCAL(b) (5 * 64 * TP_ + (b) * 192)
#define SM_T      (5 * 64 * TP_ + 384)
#define SM_R      (SM_T + 64)
#define SM_L      (SM_R + 64)
#define SM_FLOATS (SM_L + 64)

__device__ __forceinline__ void prefetch_tile(float* smf, int b, int h, int j0, int tid) {
    uint32_t kbase = (uint32_t)__cvta_generic_to_shared(smf + SM_KTX(b));
    uint32_t vbase = (uint32_t)__cvta_generic_to_shared(smf + SM_VTX(b));
    #pragma unroll
    for (int e = tid; e < 64 * 32; e += 256) {
        int r = e >> 5, c4 = (e & 31) * 4;
        CP_ASYNC16(kbase + (uint32_t)(r * TP_ + c4) * 4,
                   &g_adjpx[((size_t)h * N_ + j0 + r) * (2 * M_) + c4]);
        CP_ASYNC16(vbase + (uint32_t)(r * TP_ + c4) * 4,
                   &g_WhTx[((size_t)h * D_ + r) * (2 * N_) + 2 * j0 + c4]);
    }
    if (tid < 16) {
        uint32_t sbase = (uint32_t)__cvta_generic_to_shared(smf + SM_SCAL(b));
        CP_ASYNC16(sbase + tid * 16,       &g_f2[h * N_ + j0 + tid * 4]);
        CP_ASYNC16(sbase + 256 + tid * 16, &g_u [h * N_ + j0 + tid * 4]);
        CP_ASYNC16(sbase + 512 + tid * 16, &g_w [h * N_ + j0 + tid * 4]);
    }
    CP_COMMIT();
}

__global__ void __launch_bounds__(256) flash_kernel() {
    extern __shared__ float smf[];

    const int h  = blockIdx.y;
    const int i0 = blockIdx.x * 64;
    const int sp = blockIdx.z;
    const int tid = threadIdx.x;
    const int w = tid >> 5, lane = tid & 31;
    const int gid = lane >> 2, tig = lane & 3;
    const int mw = (w & 3) * 16, nh = (w >> 2) * 32;
    const int r0 = mw + gid, r1 = r0 + 8;

    const int jt0 = sp * 32;
    prefetch_tile(smf, 0, h, jt0 * 64, tid);

    // Q fragments: registers, loaded once (reused for all 32 j-tiles)
    uint32_t qh[8][4], ql[8][4];
    {
        const size_t base0 = ((size_t)h * N_ + i0 + r0) * (2 * M_);
        const size_t base1 = ((size_t)h * N_ + i0 + r1) * (2 * M_);
        #pragma unroll
        for (int kk = 0; kk < 8; kk++) {
            float2 a0 = *(const float2*)&g_adjpx[base0 + 2 * (kk * 8 + tig)];
            float2 a1 = *(const float2*)&g_adjpx[base1 + 2 * (kk * 8 + tig)];
            float2 a2 = *(const float2*)&g_adjpx[base0 + 2 * (kk * 8 + tig + 4)];
            float2 a3 = *(const float2*)&g_adjpx[base1 + 2 * (kk * 8 + tig + 4)];
            qh[kk][0] = FU(a0.x); qh[kk][1] = FU(a1.x); qh[kk][2] = FU(a2.x); qh[kk][3] = FU(a3.x);
            ql[kk][0] = FU(a0.y); ql[kk][1] = FU(a1.y); ql[kk][2] = FU(a2.y); ql[kk][3] = FU(a3.y);
        }
    }
    if (tid < 64) {
        float f1v = g_f1[h * N_ + i0 + tid];
        smf[SM_T + tid] = -f1v;
        smf[SM_R + tid] = __expf(-0.8f * f1v);
        smf[SM_L + tid] = 0.f;
    }
    __syncthreads();
    const float t0 = smf[SM_T + r0], t1 = smf[SM_T + r1];
    const float rr0 = smf[SM_R + r0], rr1 = smf[SM_R + r1];

    float oacc[4][4] = {};
    float l0 = 0.f, l1 = 0.f;
    float* Px = smf + SM_PX;

    for (int it = 0; it < 32; it++) {
        const int b = it & 1;
        float* KTx = smf + SM_KTX(b);
        float* VTx = smf + SM_VTX(b);
        const float* f2s = smf + SM_SCAL(b);
        const float* us = f2s + 64;
        const float* ws = f2s + 128;

        CP_WAIT0();
        __syncthreads();   // buffer b landed for all; prev iter fully finished
        if (it < 31) prefetch_tile(smf, 1 - b, h, (jt0 + it + 1) * 64, tid);

        // ---- S = Q @ K^T via 3xTF32 mma (Q in regs) ----
        float sacc[4][4] = {};
        #pragma unroll
        for (int kk = 0; kk < 8; kk++) {
            const int k0 = kk * 8;
            #pragma unroll
            for (int nb = 0; nb < 4; nb++) {
                const int jc = nh + 8 * nb + gid;
                float2 b0 = *(const float2*)&KTx[jc * TP_ + 2 * (k0 + tig)];
                float2 b1 = *(const float2*)&KTx[jc * TP_ + 2 * (k0 + tig + 4)];
                uint32_t Bh[2] = {FU(b0.x), FU(b1.x)};
                uint32_t Bl[2] = {FU(b0.y), FU(b1.y)};
                mma_tf32(sacc[nb], qh[kk], Bh);
                mma_tf32(sacc[nb], qh[kk], Bl);
                mma_tf32(sacc[nb], ql[kk], Bh);
            }
        }

        // ---- factored softmax weights + P (hi/lo) to smem ----
        #pragma unroll
        for (int nb = 0; nb < 4; nb++) {
            const int cj = nh + 8 * nb + 2 * tig;
            float f2a = f2s[cj], f2b = f2s[cj + 1];
            float ua = us[cj], ub = us[cj + 1];
            float wa = ws[cj], wb = ws[cj + 1];
            float p00 = (sacc[nb][0] > 0.f) ? ((f2a > t0) ? ua : rr0 * wa) : 0.f;
            float p01 = (sacc[nb][1] > 0.f) ? ((f2b > t0) ? ub : rr0 * wb) : 0.f;
            float p10 = (sacc[nb][2] > 0.f) ? ((f2a > t1) ? ua : rr1 * wa) : 0.f;
            float p11 = (sacc[nb][3] > 0.f) ? ((f2b > t1) ? ub : rr1 * wb) : 0.f;
            l0 += p00 + p01;
            l1 += p10 + p11;
            float2 q00 = tf32split(p00), q01 = tf32split(p01);
            float2 q10 = tf32split(p10), q11 = tf32split(p11);
            *(float4*)&Px[r0 * TP_ + 2 * cj] = make_float4(q00.x, q00.y, q01.x, q01.y);
            *(float4*)&Px[r1 * TP_ + 2 * cj] = make_float4(q10.x, q10.y, q11.x, q11.y);
        }
        __syncthreads();   // Px visible to all warps

        // ---- O += P @ V via 3xTF32 mma ----
        #pragma unroll
        for (int kk = 0; kk < 8; kk++) {
            const int k0 = kk * 8;
            float2 a0 = *(const float2*)&Px[r0 * TP_ + 2 * (k0 + tig)];
            float2 a1 = *(const float2*)&Px[r1 * TP_ + 2 * (k0 + tig)];
            float2 a2 = *(const float2*)&Px[r0 * TP_ + 2 * (k0 + tig + 4)];
            float2 a3 = *(const float2*)&Px[r1 * TP_ + 2 * (k0 + tig + 4)];
            uint32_t Ah[4] = {FU(a0.x), FU(a1.x), FU(a2.x), FU(a3.x)};
            uint32_t Al[4] = {FU(a0.y), FU(a1.y), FU(a2.y), FU(a3.y)};
            #pragma unroll
            for (int nb = 0; nb < 4; nb++) {
                const int dc = nh + 8 * nb + gid;
                float2 b0 = *(const float2*)&VTx[dc * TP_ + 2 * (k0 + tig)];
                float2 b1 = *(const float2*)&VTx[dc * TP_ + 2 * (k0 + tig + 4)];
                uint32_t Bh[2] = {FU(b0.x), FU(b1.x)};
                uint32_t Bl[2] = {FU(b0.y), FU(b1.y)};
                mma_tf32(oacc[nb], Ah, Bh);
                mma_tf32(oacc[nb], Ah, Bl);
                mma_tf32(oacc[nb], Al, Bh);
            }
        }
    }

    // l: reduce within quad (lanes sharing rows), combine across warps in smem
    l0 += __shfl_xor_sync(0xffffffffu, l0, 1);
    l0 += __shfl_xor_sync(0xffffffffu, l0, 2);
    l1 += __shfl_xor_sync(0xffffffffu, l1, 1);
    l1 += __shfl_xor_sync(0xffffffffu, l1, 2);
    if (tig == 0) {
        atomicAdd(&smf[SM_L + r0], l0);
        atomicAdd(&smf[SM_L + r1], l1);
    }
    __syncthreads();

    const int rowb = (sp * H_ + h) * N_ + i0;
    if (tid < 64) g_pl[rowb + tid] = smf[SM_L + tid];

    #pragma unroll
    for (int nb = 0; nb < 4; nb++) {
        const int dc = nh + 8 * nb + 2 * tig;
        *(float2*)&g_po[(size_t)(rowb + r0) * D_ + dc] = make_float2(oacc[nb][0], oacc[nb][1]);
        *(float2*)&g_po[(size_t)(rowb + r1) * D_ + dc] = make_float2(oacc[nb][2], oacc[nb][3]);
    }
}

// ---------------------------------------------------------------------------
// K4b: merge the two KV splits, normalize, elu.  One thread per (h,n,d4).
// ---------------------------------------------------------------------------
__global__ void merge_kernel() {
    int idx = blockIdx.x * 256 + threadIdx.x;     // < H*N*16
    int d4 = (idx & 15) * 4;
    int hn = idx >> 4;
    float inv = 1.f / (g_pl[hn] + g_pl[HN_ + hn]);
    float4 o1 = *(const float4*)&g_po[(size_t)hn * D_ + d4];
    float4 o2 = *(const float4*)&g_po[(size_t)(HN_ + hn) * D_ + d4];
    float4 v;
    v.x = (o1.x + o2.x) * inv;
    v.y = (o1.y + o2.y) * inv;
    v.z = (o1.z + o2.z) * inv;
    v.w = (o1.w + o2.w) * inv;
    v.x = (v.x > 0.f) ? v.x : (__expf(v.x) - 1.f);
    v.y = (v.y > 0.f) ? v.y : (__expf(v.y) - 1.f);
    v.z = (v.z > 0.f) ? v.z : (__expf(v.z) - 1.f);
    v.w = (v.w > 0.f) ? v.w : (__expf(v.w) - 1.f);
    *(float4*)&g_head[(size_t)hn * D_ + d4] = v;
}

// ---------------------------------------------------------------------------
// K5: out = leaky( cat(heads) @ Wd + bd ).  Grid N/64, 256 threads.
// ---------------------------------------------------------------------------
__global__ void final_kernel(const float* __restrict__ Wd,
                             const float* __restrict__ bd,
                             float* __restrict__ out) {
    __shared__ float AT[64][68];
    __shared__ float Ws[64][64];
    const int n0 = blockIdx.x * 64;
    const int tid = threadIdx.x;
    const int ty = tid >> 4, tx = tid & 15;

    float acc[4][4] = {};

    for (int h = 0; h < H_; h++) {
        __syncthreads();
        for (int e = tid; e < 64 * 16; e += 256) {
            int r = e >> 4, k4 = (e & 15) * 4;
            float4 a = *(const float4*)&g_head[((size_t)h * N_ + n0 + r) * D_ + k4];
            AT[k4 + 0][r] = a.x;
            AT[k4 + 1][r] = a.y;
            AT[k4 + 2][r] = a.z;
            AT[k4 + 3][r] = a.w;
        }
        for (int e = tid; e < 64 * 16; e += 256) {
            int rr = e >> 4, c4 = (e & 15) * 4;
            *(float4*)&Ws[rr][c4] = *(const float4*)&Wd[(size_t)(h * 64 + rr) * D_ + c4];
        }
        __syncthreads();
        #pragma unroll 8
        for (int k = 0; k < 64; k++) {
            float4 a = *(float4*)&AT[k][4 * ty];
            float4 b = *(float4*)&Ws[k][4 * tx];
            acc[0][0] += a.x * b.x; acc[0][1] += a.x * b.y; acc[0][2] += a.x * b.z; acc[0][3] += a.x * b.w;
            acc[1][0] += a.y * b.x; acc[1][1] += a.y * b.y; acc[1][2] += a.y * b.z; acc[1][3] += a.y * b.w;
            acc[2][0] += a.z * b.x; acc[2][1] += a.z * b.y; acc[2][2] += a.z * b.z; acc[2][3] += a.z * b.w;
            acc[3][0] += a.w * b.x; acc[3][1] += a.w * b.y; acc[3][2] += a.w * b.z; acc[3][3] += a.w * b.w;
        }
    }
    #pragma unroll
    for (int j = 0; j < 4; j++) {
        float b = bd[4 * tx + j];
        #pragma unroll
        for (int i = 0; i < 4; i++) {
            float v = acc[i][j] + b;
            v = (v > 0.f) ? v : SLOPE_ * v;
            out[(size_t)(n0 + 4 * ty + i) * D_ + 4 * tx + j] = v;
        }
    }
}

// ---------------------------------------------------------------------------
extern "C" void kernel_launch(void* const* d_in, const int* in_sizes, int n_in,
                              void* d_out, int out_size) {
    const float* x    = (const float*)d_in[0];
    const float* mask = (const float*)d_in[1];
    const float* adj  = (const float*)d_in[2];
    const float* W    = (const float*)d_in[3];
    const float* a1   = (const float*)d_in[4];
    const float* a2   = (const float*)d_in[5];
    const float* aw   = (const float*)d_in[6];
    const float* Wd   = (const float*)d_in[7];
    const float* bd   = (const float*)d_in[8];
    float* out        = (float*)d_out;

    cudaFuncSetAttribute(flash_kernel,
                         cudaFuncAttributeMaxDynamicSharedMemorySize,
                         SM_FLOATS * (int)sizeof(float));

    wh_kernel<<<dim3(N_ / 64, H_), 256>>>(x, mask, W);
    f12_kernel<<<(H_ * N_) / 8, 256>>>(a1, a2);
    adjp_kernel<<<(N_ * M_) / 8, 256>>>(adj, aw);
    flash_kernel<<<dim3(N_ / 64, H_, 2), 256, SM_FLOATS * (int)sizeof(float)>>>();
    merge_kernel<<<(HN_ * 16) / 256, 256>>>();
    final_kernel<<<N_ / 64, 256>>>(Wd, bd, out);
}

// round 12
// speedup vs baseline: 1.2433x; 1.0169x over previous
#include <cuda_runtime.h>
#include <cstdint>

// ---------------------------------------------------------------------------
// GraphAttentionWithMask: 4-head GAT, N=4096, F=512, D=64, E=128, M=64
//
//  K1 wh_kernel    : Wh = (mask*x) @ W[h];  writes Wh + WhTx (tf32 hi/lo interleaved)
//  K2 f12_kernel   : f1/f2[h][n]; u=exp(f2), w=exp(0.2*f2)
//  K3 adjp_kernel  : adjpx[h][n][2m] = tf32 hi/lo of adj[n][m]·aw[h]
//  K4 flash_kernel : masked attention, factored softmax, 3xTF32 mma.sync,
//                    Q in registers, cp.async double-buffered 32-wide j-tiles,
//                    89 KB smem -> 2 CTAs/SM, split-KV x2
//  K4b merge_kernel: (o1+o2)/(l1+l2), elu
//  K5 final_kernel : out = leaky(cat(heads) @ Wd + bd)
// ---------------------------------------------------------------------------

#define N_  4096
#define F_  512
#define D_  64
#define H_  4
#define E_  128
#define M_  64
#define HN_ (H_ * N_)
#define SLOPE_ 0.2f

__device__ __forceinline__ float2 tf32split(float a) {
    uint32_t hb;
    asm("cvt.rna.tf32.f32 %0, %1;" : "=r"(hb) : "f"(a));
    float hf = __uint_as_float(hb);
    return make_float2(hf, a - hf);
}

__device__ __forceinline__ void mma_tf32(float* d, const uint32_t* a, const uint32_t* b) {
    asm volatile(
        "mma.sync.aligned.m16n8k8.row.col.f32.tf32.tf32.f32 "
        "{%0,%1,%2,%3}, {%4,%5,%6,%7}, {%8,%9}, {%0,%1,%2,%3};"
        : "+f"(d[0]), "+f"(d[1]), "+f"(d[2]), "+f"(d[3])
        : "r"(a[0]), "r"(a[1]), "r"(a[2]), "r"(a[3]), "r"(b[0]), "r"(b[1]));
}

#define FU(x) __float_as_uint(x)

#define CP_ASYNC16(smaddr, gptr) \
    asm volatile("cp.async.cg.shared.global [%0], [%1], 16;" \
                 :: "r"(smaddr), "l"(gptr))
#define CP_COMMIT() asm volatile("cp.async.commit_group;")
#define CP_WAIT0()  asm volatile("cp.async.wait_group 0;")

__device__ float g_Wh   [H_ * N_ * D_];
__device__ float g_WhTx [H_ * D_ * 2 * N_];   // [h][d][2n] interleaved hi/lo
__device__ float g_adjpx[H_ * N_ * 2 * M_];   // [h][n][2m] interleaved hi/lo
__device__ float g_f1   [H_ * N_];
__device__ float g_f2   [H_ * N_];
__device__ float g_u    [H_ * N_];            // exp(f2)
__device__ float g_w    [H_ * N_];            // exp(0.2 f2)
__device__ float g_head [H_ * N_ * D_];
__device__ float g_po   [2 * H_ * N_ * D_];   // split-KV partials
__device__ float g_pl   [2 * H_ * N_];

// ---------------------------------------------------------------------------
// K1: Wh = (mask*x) @ W[h].  Grid (N/64, H), 256 threads, 4x4 reg tile.
// ---------------------------------------------------------------------------
__global__ void wh_kernel(const float* __restrict__ x,
                          const float* __restrict__ mask,
                          const float* __restrict__ W) {
    __shared__ float xT[64][68];
    __shared__ float Ws[64][64];
    const int h  = blockIdx.y;
    const int n0 = blockIdx.x * 64;
    const int tid = threadIdx.x;
    const int ty = tid >> 4, tx = tid & 15;

    float acc[4][4] = {};

    for (int f0 = 0; f0 < F_; f0 += 64) {
        __syncthreads();
        for (int e = tid; e < 64 * 16; e += 256) {
            int r = e >> 4, k4 = (e & 15) * 4;
            float mk = mask[n0 + r];
            float4 xv = *(const float4*)&x[(size_t)(n0 + r) * F_ + f0 + k4];
            xT[k4 + 0][r] = xv.x * mk;
            xT[k4 + 1][r] = xv.y * mk;
            xT[k4 + 2][r] = xv.z * mk;
            xT[k4 + 3][r] = xv.w * mk;
        }
        for (int e = tid; e < 64 * 16; e += 256) {
            int rr = e >> 4, c4 = (e & 15) * 4;
            *(float4*)&Ws[rr][c4] =
                *(const float4*)&W[((size_t)h * F_ + f0 + rr) * D_ + c4];
        }
        __syncthreads();
        #pragma unroll 8
        for (int k = 0; k < 64; k++) {
            float4 a = *(float4*)&xT[k][4 * ty];
            float4 b = *(float4*)&Ws[k][4 * tx];
            acc[0][0] += a.x * b.x; acc[0][1] += a.x * b.y; acc[0][2] += a.x * b.z; acc[0][3] += a.x * b.w;
            acc[1][0] += a.y * b.x; acc[1][1] += a.y * b.y; acc[1][2] += a.y * b.z; acc[1][3] += a.y * b.w;
            acc[2][0] += a.z * b.x; acc[2][1] += a.z * b.y; acc[2][2] += a.z * b.z; acc[2][3] += a.z * b.w;
            acc[3][0] += a.w * b.x; acc[3][1] += a.w * b.y; acc[3][2] += a.w * b.z; acc[3][3] += a.w * b.w;
        }
    }
    #pragma unroll
    for (int i = 0; i < 4; i++)
        #pragma unroll
        for (int j = 0; j < 4; j++)
            g_Wh[((size_t)h * N_ + n0 + 4 * ty + i) * D_ + 4 * tx + j] = acc[i][j];
    // transposed hi/lo interleaved copy for flash PV mma (B operand)
    #pragma unroll
    for (int j = 0; j < 4; j++) {
        float2 s0 = tf32split(acc[0][j]);
        float2 s1 = tf32split(acc[1][j]);
        float2 s2 = tf32split(acc[2][j]);
        float2 s3 = tf32split(acc[3][j]);
        size_t base = ((size_t)h * D_ + 4 * tx + j) * (2 * N_) + 2 * (n0 + 4 * ty);
        *(float4*)&g_WhTx[base]     = make_float4(s0.x, s0.y, s1.x, s1.y);
        *(float4*)&g_WhTx[base + 4] = make_float4(s2.x, s2.y, s3.x, s3.y);
    }
}

// ---------------------------------------------------------------------------
// K2: f1/f2 = Wh @ a1/a2; u = exp(f2), w = exp(0.2 f2).  One warp per (h,n).
// ---------------------------------------------------------------------------
__global__ void f12_kernel(const float* __restrict__ a1,
                           const float* __restrict__ a2) {
    int w = (blockIdx.x * blockDim.x + threadIdx.x) >> 5;
    int lane = threadIdx.x & 31;
    int h = w / N_, n = w % N_;
    const float2 v  = ((const float2*)&g_Wh[((size_t)h * N_ + n) * D_])[lane];
    const float2 w1 = ((const float2*)&a1[h * D_])[lane];
    const float2 w2 = ((const float2*)&a2[h * D_])[lane];
    float s1 = v.x * w1.x + v.y * w1.y;
    float s2 = v.x * w2.x + v.y * w2.y;
    #pragma unroll
    for (int off = 16; off; off >>= 1) {
        s1 += __shfl_xor_sync(0xffffffffu, s1, off);
        s2 += __shfl_xor_sync(0xffffffffu, s2, off);
    }
    if (lane == 0) {
        g_f1[h * N_ + n] = s1;
        g_f2[h * N_ + n] = s2;
        g_u [h * N_ + n] = __expf(s2);
        g_w [h * N_ + n] = __expf(0.2f * s2);
    }
}

// ---------------------------------------------------------------------------
// K3: adjpx[h][n][2m] = tf32 hi/lo of adj[n][m]·aw[h].  One warp per (n,m).
// ---------------------------------------------------------------------------
__global__ void adjp_kernel(const float* __restrict__ adj,
                            const float* __restrict__ aw) {
    __shared__ float aws[H_ * E_];
    int tid = threadIdx.x;
    if (tid < H_ * E_) aws[tid] = aw[tid];
    if (tid + 256 < H_ * E_) aws[tid + 256] = aw[tid + 256];
    __syncthreads();

    int w = (blockIdx.x * blockDim.x + tid) >> 5;   // 0..N*M-1
    int lane = tid & 31;
    int n = w / M_, m = w % M_;
    float4 v = ((const float4*)&adj[(size_t)(n * M_ + m) * E_])[lane];
    float s[H_];
    #pragma unroll
    for (int h = 0; h < H_; h++) {
        const float4 aw4 = ((const float4*)&aws[h * E_])[lane];
        s[h] = v.x * aw4.x + v.y * aw4.y + v.z * aw4.z + v.w * aw4.w;
    }
    #pragma unroll
    for (int off = 16; off; off >>= 1) {
        #pragma unroll
        for (int h = 0; h < H_; h++)
            s[h] += __shfl_xor_sync(0xffffffffu, s[h], off);
    }
    if (lane == 0) {
        #pragma unroll
        for (int h = 0; h < H_; h++) {
            float2 sp = tf32split(s[h]);
            *(float2*)&g_adjpx[((size_t)h * N_ + n) * (2 * M_) + 2 * m] = sp;
        }
    }
}

// ---------------------------------------------------------------------------
// K4: flash attention, 3xTF32 mma, Q in regs, cp.async double buffer,
// 32-wide j-tiles (64 iterations), ~89 KB smem -> 2 CTAs/SM.
// Grid (N/64, H, 2), 256 threads = 8 warps.
// Warp w: m-band (w&3)*16; S col-half (w>>2)*16; PV d-half (w>>2)*32.
// ---------------------------------------------------------------------------
#define TPK_ 136   // K tile pitch: 32 rows x (2*64 + 8)
#define TPV_ 68    // V tile pitch: 64 rows x (2*32 + 4)
#define TPP_ 68    // P tile pitch: 64 rows x (2*32 + 4)
#define SM_KTX(b)  ((b) * 32 * TPK_)
#define SM_VTX(b)  (2 * 32 * TPK_ + (b) * 64 * TPV_)
#define SM_PX      (2 * 32 * TPK_ + 2 * 64 * TPV_)
#define SM_SCAL(b) (SM_PX + 64 * TPP_ + (b) * 96)
#define SM_T       (SM_PX + 64 * TPP_ + 192)
#define SM_R       (SM_T + 64)
#define SM_L       (SM_R + 64)
#define SM_FLOATS  (SM_L + 64)

__device__ __forceinline__ void prefetch_tile(float* smf, int b, int h, int j0, int tid) {
    uint32_t kbase = (uint32_t)__cvta_generic_to_shared(smf + SM_KTX(b));
    uint32_t vbase = (uint32_t)__cvta_generic_to_shared(smf + SM_VTX(b));
    #pragma unroll
    for (int e = tid; e < 32 * 32; e += 256) {   // K: 32 rows x 32 chunks
        int r = e >> 5, c4 = (e & 31) * 4;
        CP_ASYNC16(kbase + (uint32_t)(r * TPK_ + c4) * 4,
                   &g_adjpx[((size_t)h * N_ + j0 + r) * (2 * M_) + c4]);
    }
    #pragma unroll
    for (int e = tid; e < 64 * 16; e += 256) {   // V: 64 rows x 16 chunks
        int r = e >> 4, c4 = (e & 15) * 4;
        CP_ASYNC16(vbase + (uint32_t)(r * TPV_ + c4) * 4,
                   &g_WhTx[((size_t)h * D_ + r) * (2 * N_) + 2 * j0 + c4]);
    }
    if (tid < 8) {
        uint32_t sbase = (uint32_t)__cvta_generic_to_shared(smf + SM_SCAL(b));
        CP_ASYNC16(sbase + tid * 16,       &g_f2[h * N_ + j0 + tid * 4]);
        CP_ASYNC16(sbase + 128 + tid * 16, &g_u [h * N_ + j0 + tid * 4]);
        CP_ASYNC16(sbase + 256 + tid * 16, &g_w [h * N_ + j0 + tid * 4]);
    }
    CP_COMMIT();
}

__global__ void __launch_bounds__(256, 2) flash_kernel() {
    extern __shared__ float smf[];

    const int h  = blockIdx.y;
    const int i0 = blockIdx.x * 64;
    const int sp = blockIdx.z;
    const int tid = threadIdx.x;
    const int w = tid >> 5, lane = tid & 31;
    const int gid = lane >> 2, tig = lane & 3;
    const int mw = (w & 3) * 16;          // m-band
    const int ch = (w >> 2) * 16;         // S col-half (16 j cols)
    const int nh2 = (w >> 2) * 32;        // PV d-half (32 dims)
    const int r0 = mw + gid, r1 = r0 + 8;

    const int j0base = sp * 2048;
    prefetch_tile(smf, 0, h, j0base, tid);

    // Q fragments: registers, loaded once (reused for all 64 j-tiles)
    uint32_t qh[8][4], ql[8][4];
    {
        const size_t base0 = ((size_t)h * N_ + i0 + r0) * (2 * M_);
        const size_t base1 = ((size_t)h * N_ + i0 + r1) * (2 * M_);
        #pragma unroll
        for (int kk = 0; kk < 8; kk++) {
            float2 a0 = *(const float2*)&g_adjpx[base0 + 2 * (kk * 8 + tig)];
            float2 a1 = *(const float2*)&g_adjpx[base1 + 2 * (kk * 8 + tig)];
            float2 a2 = *(const float2*)&g_adjpx[base0 + 2 * (kk * 8 + tig + 4)];
            float2 a3 = *(const float2*)&g_adjpx[base1 + 2 * (kk * 8 + tig + 4)];
            qh[kk][0] = FU(a0.x); qh[kk][1] = FU(a1.x); qh[kk][2] = FU(a2.x); qh[kk][3] = FU(a3.x);
            ql[kk][0] = FU(a0.y); ql[kk][1] = FU(a1.y); ql[kk][2] = FU(a2.y); ql[kk][3] = FU(a3.y);
        }
    }
    if (tid < 64) {
        float f1v = g_f1[h * N_ + i0 + tid];
        smf[SM_T + tid] = -f1v;
        smf[SM_R + tid] = __expf(-0.8f * f1v);
        smf[SM_L + tid] = 0.f;
    }
    __syncthreads();
    const float t0 = smf[SM_T + r0], t1 = smf[SM_T + r1];
    const float rr0 = smf[SM_R + r0], rr1 = smf[SM_R + r1];

    float oacc[4][4] = {};
    float l0 = 0.f, l1 = 0.f;
    float* Px = smf + SM_PX;

    for (int it = 0; it < 64; it++) {
        const int b = it & 1;
        float* KTx = smf + SM_KTX(b);
        float* VTx = smf + SM_VTX(b);
        const float* f2s = smf + SM_SCAL(b);
        const float* us = f2s + 32;
        const float* ws = f2s + 64;

        CP_WAIT0();
        __syncthreads();   // buffer b landed; prev iter's use of this buffer done
        if (it < 63) prefetch_tile(smf, 1 - b, h, j0base + (it + 1) * 32, tid);

        // ---- S = Q @ K^T via 3xTF32 mma (Q in regs), 16 cols per warp ----
        float sacc[2][4] = {};
        #pragma unroll
        for (int kk = 0; kk < 8; kk++) {
            const int k0 = kk * 8;
            #pragma unroll
            for (int nb = 0; nb < 2; nb++) {
                const int jc = ch + 8 * nb + gid;
                float2 b0 = *(const float2*)&KTx[jc * TPK_ + 2 * (k0 + tig)];
                float2 b1 = *(const float2*)&KTx[jc * TPK_ + 2 * (k0 + tig + 4)];
                uint32_t Bh[2] = {FU(b0.x), FU(b1.x)};
                uint32_t Bl[2] = {FU(b0.y), FU(b1.y)};
                mma_tf32(sacc[nb], qh[kk], Bh);
                mma_tf32(sacc[nb], qh[kk], Bl);
                mma_tf32(sacc[nb], ql[kk], Bh);
            }
        }

        // ---- factored softmax weights + P (hi/lo) to smem ----
        #pragma unroll
        for (int nb = 0; nb < 2; nb++) {
            const int cj = ch + 8 * nb + 2 * tig;
            float f2a = f2s[cj], f2b = f2s[cj + 1];
            float ua = us[cj], ub = us[cj + 1];
            float wa = ws[cj], wb = ws[cj + 1];
            float p00 = (sacc[nb][0] > 0.f) ? ((f2a > t0) ? ua : rr0 * wa) : 0.f;
            float p01 = (sacc[nb][1] > 0.f) ? ((f2b > t0) ? ub : rr0 * wb) : 0.f;
            float p10 = (sacc[nb][2] > 0.f) ? ((f2a > t1) ? ua : rr1 * wa) : 0.f;
            float p11 = (sacc[nb][3] > 0.f) ? ((f2b > t1) ? ub : rr1 * wb) : 0.f;
            l0 += p00 + p01;
            l1 += p10 + p11;
            float2 q00 = tf32split(p00), q01 = tf32split(p01);
            float2 q10 = tf32split(p10), q11 = tf32split(p11);
            *(float4*)&Px[r0 * TPP_ + 2 * cj] = make_float4(q00.x, q00.y, q01.x, q01.y);
            *(float4*)&Px[r1 * TPP_ + 2 * cj] = make_float4(q10.x, q10.y, q11.x, q11.y);
        }
        __syncthreads();   // Px visible to all warps

        // ---- O += P @ V via 3xTF32 mma (k = 32 j values) ----
        #pragma unroll
        for (int kk = 0; kk < 4; kk++) {
            const int k0 = kk * 8;
            float2 a0 = *(const float2*)&Px[r0 * TPP_ + 2 * (k0 + tig)];
            float2 a1 = *(const float2*)&Px[r1 * TPP_ + 2 * (k0 + tig)];
            float2 a2 = *(const float2*)&Px[r0 * TPP_ + 2 * (k0 + tig + 4)];
            float2 a3 = *(const float2*)&Px[r1 * TPP_ + 2 * (k0 + tig + 4)];
            uint32_t Ah[4] = {FU(a0.x), FU(a1.x), FU(a2.x), FU(a3.x)};
            uint32_t Al[4] = {FU(a0.y), FU(a1.y), FU(a2.y), FU(a3.y)};
            #pragma unroll
            for (int nb = 0; nb < 4; nb++) {
                const int dc = nh2 + 8 * nb + gid;
                float2 b0 = *(const float2*)&VTx[dc * TPV_ + 2 * (k0 + tig)];
                float2 b1 = *(const float2*)&VTx[dc * TPV_ + 2 * (k0 + tig + 4)];
                uint32_t Bh[2] = {FU(b0.x), FU(b1.x)};
                uint32_t Bl[2] = {FU(b0.y), FU(b1.y)};
                mma_tf32(oacc[nb], Ah, Bh);
                mma_tf32(oacc[nb], Ah, Bl);
                mma_tf32(oacc[nb], Al, Bh);
            }
        }
    }

    // l: reduce within quad (lanes sharing rows), combine across warps in smem
    l0 += __shfl_xor_sync(0xffffffffu, l0, 1);
    l0 += __shfl_xor_sync(0xffffffffu, l0, 2);
    l1 += __shfl_xor_sync(0xffffffffu, l1, 1);
    l1 += __shfl_xor_sync(0xffffffffu, l1, 2);
    if (tig == 0) {
        atomicAdd(&smf[SM_L + r0], l0);
        atomicAdd(&smf[SM_L + r1], l1);
    }
    __syncthreads();

    const int rowb = (sp * H_ + h) * N_ + i0;
    if (tid < 64) g_pl[rowb + tid] = smf[SM_L + tid];

    #pragma unroll
    for (int nb = 0; nb < 4; nb++) {
        const int dc = nh2 + 8 * nb + 2 * tig;
        *(float2*)&g_po[(size_t)(rowb + r0) * D_ + dc] = make_float2(oacc[nb][0], oacc[nb][1]);
        *(float2*)&g_po[(size_t)(rowb + r1) * D_ + dc] = make_float2(oacc[nb][2], oacc[nb][3]);
    }
}

// ---------------------------------------------------------------------------
// K4b: merge the two KV splits, normalize, elu.  One thread per (h,n,d4).
// ---------------------------------------------------------------------------
__global__ void merge_kernel() {
    int idx = blockIdx.x * 256 + threadIdx.x;     // < H*N*16
    int d4 = (idx & 15) * 4;
    int hn = idx >> 4;
    float inv = 1.f / (g_pl[hn] + g_pl[HN_ + hn]);
    float4 o1 = *(const float4*)&g_po[(size_t)hn * D_ + d4];
    float4 o2 = *(const float4*)&g_po[(size_t)(HN_ + hn) * D_ + d4];
    float4 v;
    v.x = (o1.x + o2.x) * inv;
    v.y = (o1.y + o2.y) * inv;
    v.z = (o1.z + o2.z) * inv;
    v.w = (o1.w + o2.w) * inv;
    v.x = (v.x > 0.f) ? v.x : (__expf(v.x) - 1.f);
    v.y = (v.y > 0.f) ? v.y : (__expf(v.y) - 1.f);
    v.z = (v.z > 0.f) ? v.z : (__expf(v.z) - 1.f);
    v.w = (v.w > 0.f) ? v.w : (__expf(v.w) - 1.f);
    *(float4*)&g_head[(size_t)hn * D_ + d4] = v;
}

// ---------------------------------------------------------------------------
// K5: out = leaky( cat(heads) @ Wd + bd ).  Grid N/64, 256 threads.
// ---------------------------------------------------------------------------
__global__ void final_kernel(const float* __restrict__ Wd,
                             const float* __restrict__ bd,
                             float* __restrict__ out) {
    __shared__ float AT[64][68];
    __shared__ float Ws[64][64];
    const int n0 = blockIdx.x * 64;
    const int tid = threadIdx.x;
    const int ty = tid >> 4, tx = tid & 15;

    float acc[4][4] = {};

    for (int h = 0; h < H_; h++) {
        __syncthreads();
        for (int e = tid; e < 64 * 16; e += 256) {
            int r = e >> 4, k4 = (e & 15) * 4;
            float4 a = *(const float4*)&g_head[((size_t)h * N_ + n0 + r) * D_ + k4];
            AT[k4 + 0][r] = a.x;
            AT[k4 + 1][r] = a.y;
            AT[k4 + 2][r] = a.z;
            AT[k4 + 3][r] = a.w;
        }
        for (int e = tid; e < 64 * 16; e += 256) {
            int rr = e >> 4, c4 = (e & 15) * 4;
            *(float4*)&Ws[rr][c4] = *(const float4*)&Wd[(size_t)(h * 64 + rr) * D_ + c4];
        }
        __syncthreads();
        #pragma unroll 8
        for (int k = 0; k < 64; k++) {
            float4 a = *(float4*)&AT[k][4 * ty];
            float4 b = *(float4*)&Ws[k][4 * tx];
            acc[0][0] += a.x * b.x; acc[0][1] += a.x * b.y; acc[0][2] += a.x * b.z; acc[0][3] += a.x * b.w;
            acc[1][0] += a.y * b.x; acc[1][1] += a.y * b.y; acc[1][2] += a.y * b.z; acc[1][3] += a.y * b.w;
            acc[2][0] += a.z * b.x; acc[2][1] += a.z * b.y; acc[2][2] += a.z * b.z; acc[2][3] += a.z * b.w;
            acc[3][0] += a.w * b.x; acc[3][1] += a.w * b.y; acc[3][2] += a.w * b.z; acc[3][3] += a.w * b.w;
        }
    }
    #pragma unroll
    for (int j = 0; j < 4; j++) {
        float b = bd[4 * tx + j];
        #pragma unroll
        for (int i = 0; i < 4; i++) {
            float v = acc[i][j] + b;
            v = (v > 0.f) ? v : SLOPE_ * v;
            out[(size_t)(n0 + 4 * ty + i) * D_ + 4 * tx + j] = v;
        }
    }
}

// ---------------------------------------------------------------------------
extern "C" void kernel_launch(void* const* d_in, const int* in_sizes, int n_in,
                              void* d_out, int out_size) {
    const float* x    = (const float*)d_in[0];
    const float* mask = (const float*)d_in[1];
    const float* adj  = (const float*)d_in[2];
    const float* W    = (const float*)d_in[3];
    const float* a1   = (const float*)d_in[4];
    const float* a2   = (const float*)d_in[5];
    const float* aw   = (const float*)d_in[6];
    const float* Wd   = (const float*)d_in[7];
    const float* bd   = (const float*)d_in[8];
    float* out        = (float*)d_out;

    cudaFuncSetAttribute(flash_kernel,
                         cudaFuncAttributeMaxDynamicSharedMemorySize,
                         SM_FLOATS * (int)sizeof(float));

    wh_kernel<<<dim3(N_ / 64, H_), 256>>>(x, mask, W);
    f12_kernel<<<(H_ * N_) / 8, 256>>>(a1, a2);
    adjp_kernel<<<(N_ * M_) / 8, 256>>>(adj, aw);
    flash_kernel<<<dim3(N_ / 64, H_, 2), 256, SM_FLOATS * (int)sizeof(float)>>>();
    merge_kernel<<<(HN_ * 16) / 256, 256>>>();
    final_kernel<<<N_ / 64, 256>>>(Wd, bd, out);
}

// round 13
// speedup vs baseline: 1.4545x; 1.1699x over previous
#include <cuda_runtime.h>
#include <cstdint>

// ---------------------------------------------------------------------------
// GraphAttentionWithMask: 4-head GAT, N=4096, F=512, D=64, E=128, M=64
//
//  K1 wh_kernel    : Wh = (mask*x) @ W[h];  writes Wh + WhTx (tf32 hi/lo interleaved)
//  K2 f12_kernel   : f1/f2[h][n]; u=exp(f2), w=exp(0.2*f2)
//  K3 adjp_kernel  : adjpx[h][n][2m] = tf32 hi/lo of adj[n][m]·aw[h]
//  K4 flash_kernel : masked attention, factored softmax with tf32-quantized P
//                    (self-consistent l), S via 3xTF32 mma, PV via 2 mma
//                    (P exact in tf32), Q in regs, cp.async double buffer,
//                    ~80 KB smem -> 2 CTAs/SM, split-KV x2
//  K4b merge_kernel: (o1+o2)/(l1+l2), elu
//  K5 final_kernel : out = leaky(cat(heads) @ Wd + bd)
// ---------------------------------------------------------------------------

#define N_  4096
#define F_  512
#define D_  64
#define H_  4
#define E_  128
#define M_  64
#define HN_ (H_ * N_)
#define SLOPE_ 0.2f

__device__ __forceinline__ float2 tf32split(float a) {
    uint32_t hb;
    asm("cvt.rna.tf32.f32 %0, %1;" : "=r"(hb) : "f"(a));
    float hf = __uint_as_float(hb);
    return make_float2(hf, a - hf);
}

__device__ __forceinline__ float tf32round(float a) {
    uint32_t hb;
    asm("cvt.rna.tf32.f32 %0, %1;" : "=r"(hb) : "f"(a));
    return __uint_as_float(hb);
}

__device__ __forceinline__ void mma_tf32(float* d, const uint32_t* a, const uint32_t* b) {
    asm volatile(
        "mma.sync.aligned.m16n8k8.row.col.f32.tf32.tf32.f32 "
        "{%0,%1,%2,%3}, {%4,%5,%6,%7}, {%8,%9}, {%0,%1,%2,%3};"
        : "+f"(d[0]), "+f"(d[1]), "+f"(d[2]), "+f"(d[3])
        : "r"(a[0]), "r"(a[1]), "r"(a[2]), "r"(a[3]), "r"(b[0]), "r"(b[1]));
}

#define FU(x) __float_as_uint(x)

#define CP_ASYNC16(smaddr, gptr) \
    asm volatile("cp.async.cg.shared.global [%0], [%1], 16;" \
                 :: "r"(smaddr), "l"(gptr))
#define CP_COMMIT() asm volatile("cp.async.commit_group;")
#define CP_WAIT0()  asm volatile("cp.async.wait_group 0;")

__device__ float g_Wh   [H_ * N_ * D_];
__device__ float g_WhTx [H_ * D_ * 2 * N_];   // [h][d][2n] interleaved hi/lo
__device__ float g_adjpx[H_ * N_ * 2 * M_];   // [h][n][2m] interleaved hi/lo
__device__ float g_f1   [H_ * N_];
__device__ float g_f2   [H_ * N_];
__device__ float g_u    [H_ * N_];            // exp(f2)
__device__ float g_w    [H_ * N_];            // exp(0.2 f2)
__device__ float g_head [H_ * N_ * D_];
__device__ float g_po   [2 * H_ * N_ * D_];   // split-KV partials
__device__ float g_pl   [2 * H_ * N_];

// ---------------------------------------------------------------------------
// K1: Wh = (mask*x) @ W[h].  Grid (N/64, H), 256 threads, 4x4 reg tile.
// ---------------------------------------------------------------------------
__global__ void wh_kernel(const float* __restrict__ x,
                          const float* __restrict__ mask,
                          const float* __restrict__ W) {
    __shared__ float xT[64][68];
    __shared__ float Ws[64][64];
    const int h  = blockIdx.y;
    const int n0 = blockIdx.x * 64;
    const int tid = threadIdx.x;
    const int ty = tid >> 4, tx = tid & 15;

    float acc[4][4] = {};

    for (int f0 = 0; f0 < F_; f0 += 64) {
        __syncthreads();
        for (int e = tid; e < 64 * 16; e += 256) {
            int r = e >> 4, k4 = (e & 15) * 4;
            float mk = mask[n0 + r];
            float4 xv = *(const float4*)&x[(size_t)(n0 + r) * F_ + f0 + k4];
            xT[k4 + 0][r] = xv.x * mk;
            xT[k4 + 1][r] = xv.y * mk;
            xT[k4 + 2][r] = xv.z * mk;
            xT[k4 + 3][r] = xv.w * mk;
        }
        for (int e = tid; e < 64 * 16; e += 256) {
            int rr = e >> 4, c4 = (e & 15) * 4;
            *(float4*)&Ws[rr][c4] =
                *(const float4*)&W[((size_t)h * F_ + f0 + rr) * D_ + c4];
        }
        __syncthreads();
        #pragma unroll 8
        for (int k = 0; k < 64; k++) {
            float4 a = *(float4*)&xT[k][4 * ty];
            float4 b = *(float4*)&Ws[k][4 * tx];
            acc[0][0] += a.x * b.x; acc[0][1] += a.x * b.y; acc[0][2] += a.x * b.z; acc[0][3] += a.x * b.w;
            acc[1][0] += a.y * b.x; acc[1][1] += a.y * b.y; acc[1][2] += a.y * b.z; acc[1][3] += a.y * b.w;
            acc[2][0] += a.z * b.x; acc[2][1] += a.z * b.y; acc[2][2] += a.z * b.z; acc[2][3] += a.z * b.w;
            acc[3][0] += a.w * b.x; acc[3][1] += a.w * b.y; acc[3][2] += a.w * b.z; acc[3][3] += a.w * b.w;
        }
    }
    #pragma unroll
    for (int i = 0; i < 4; i++)
        #pragma unroll
        for (int j = 0; j < 4; j++)
            g_Wh[((size_t)h * N_ + n0 + 4 * ty + i) * D_ + 4 * tx + j] = acc[i][j];
    // transposed hi/lo interleaved copy for flash PV mma (B operand)
    #pragma unroll
    for (int j = 0; j < 4; j++) {
        float2 s0 = tf32split(acc[0][j]);
        float2 s1 = tf32split(acc[1][j]);
        float2 s2 = tf32split(acc[2][j]);
        float2 s3 = tf32split(acc[3][j]);
        size_t base = ((size_t)h * D_ + 4 * tx + j) * (2 * N_) + 2 * (n0 + 4 * ty);
        *(float4*)&g_WhTx[base]     = make_float4(s0.x, s0.y, s1.x, s1.y);
        *(float4*)&g_WhTx[base + 4] = make_float4(s2.x, s2.y, s3.x, s3.y);
    }
}

// ---------------------------------------------------------------------------
// K2: f1/f2 = Wh @ a1/a2; u = exp(f2), w = exp(0.2 f2).  One warp per (h,n).
// ---------------------------------------------------------------------------
__global__ void f12_kernel(const float* __restrict__ a1,
                           const float* __restrict__ a2) {
    int w = (blockIdx.x * blockDim.x + threadIdx.x) >> 5;
    int lane = threadIdx.x & 31;
    int h = w / N_, n = w % N_;
    const float2 v  = ((const float2*)&g_Wh[((size_t)h * N_ + n) * D_])[lane];
    const float2 w1 = ((const float2*)&a1[h * D_])[lane];
    const float2 w2 = ((const float2*)&a2[h * D_])[lane];
    float s1 = v.x * w1.x + v.y * w1.y;
    float s2 = v.x * w2.x + v.y * w2.y;
    #pragma unroll
    for (int off = 16; off; off >>= 1) {
        s1 += __shfl_xor_sync(0xffffffffu, s1, off);
        s2 += __shfl_xor_sync(0xffffffffu, s2, off);
    }
    if (lane == 0) {
        g_f1[h * N_ + n] = s1;
        g_f2[h * N_ + n] = s2;
        g_u [h * N_ + n] = __expf(s2);
        g_w [h * N_ + n] = __expf(0.2f * s2);
    }
}

// ---------------------------------------------------------------------------
// K3: adjpx[h][n][2m] = tf32 hi/lo of adj[n][m]·aw[h].  One warp per (n,m).
// ---------------------------------------------------------------------------
__global__ void adjp_kernel(const float* __restrict__ adj,
                            const float* __restrict__ aw) {
    __shared__ float aws[H_ * E_];
    int tid = threadIdx.x;
    if (tid < H_ * E_) aws[tid] = aw[tid];
    if (tid + 256 < H_ * E_) aws[tid + 256] = aw[tid + 256];
    __syncthreads();

    int w = (blockIdx.x * blockDim.x + tid) >> 5;   // 0..N*M-1
    int lane = tid & 31;
    int n = w / M_, m = w % M_;
    float4 v = ((const float4*)&adj[(size_t)(n * M_ + m) * E_])[lane];
    float s[H_];
    #pragma unroll
    for (int h = 0; h < H_; h++) {
        const float4 aw4 = ((const float4*)&aws[h * E_])[lane];
        s[h] = v.x * aw4.x + v.y * aw4.y + v.z * aw4.z + v.w * aw4.w;
    }
    #pragma unroll
    for (int off = 16; off; off >>= 1) {
        #pragma unroll
        for (int h = 0; h < H_; h++)
            s[h] += __shfl_xor_sync(0xffffffffu, s[h], off);
    }
    if (lane == 0) {
        #pragma unroll
        for (int h = 0; h < H_; h++) {
            float2 sp = tf32split(s[h]);
            *(float2*)&g_adjpx[((size_t)h * N_ + n) * (2 * M_) + 2 * m] = sp;
        }
    }
}

// ---------------------------------------------------------------------------
// K4: flash attention.  S via 3xTF32; P quantized to tf32 (self-consistent l)
// so PV needs only 2 mmas.  Q in regs, cp.async double buffer, 32-wide
// j-tiles, ~80 KB smem -> 2 CTAs/SM.  Grid (N/64, H, 2), 256 threads.
// Warp w: m-band (w&3)*16; S col-half (w>>2)*16; PV d-half (w>>2)*32.
// ---------------------------------------------------------------------------
#define TPK_ 136   // K tile pitch: 32 rows x (2*64 + 8)
#define TPV_ 68    // V tile pitch: 64 rows x (2*32 + 4)
#define TPP_ 36    // P tile pitch: 64 rows x (32 + 4)   (tf32 values, no lo)
#define SM_KTX(b)  ((b) * 32 * TPK_)
#define SM_VTX(b)  (2 * 32 * TPK_ + (b) * 64 * TPV_)
#define SM_PX      (2 * 32 * TPK_ + 2 * 64 * TPV_)
#define SM_SCAL(b) (SM_PX + 64 * TPP_ + (b) * 96)
#define SM_T       (SM_PX + 64 * TPP_ + 192)
#define SM_R       (SM_T + 64)
#define SM_L       (SM_R + 64)
#define SM_FLOATS  (SM_L + 64)

__device__ __forceinline__ void prefetch_tile(float* smf, int b, int h, int j0, int tid) {
    uint32_t kbase = (uint32_t)__cvta_generic_to_shared(smf + SM_KTX(b));
    uint32_t vbase = (uint32_t)__cvta_generic_to_shared(smf + SM_VTX(b));
    #pragma unroll
    for (int e = tid; e < 32 * 32; e += 256) {   // K: 32 rows x 32 chunks
        int r = e >> 5, c4 = (e & 31) * 4;
        CP_ASYNC16(kbase + (uint32_t)(r * TPK_ + c4) * 4,
                   &g_adjpx[((size_t)h * N_ + j0 + r) * (2 * M_) + c4]);
    }
    #pragma unroll
    for (int e = tid; e < 64 * 16; e += 256) {   // V: 64 rows x 16 chunks
        int r = e >> 4, c4 = (e & 15) * 4;
        CP_ASYNC16(vbase + (uint32_t)(r * TPV_ + c4) * 4,
                   &g_WhTx[((size_t)h * D_ + r) * (2 * N_) + 2 * j0 + c4]);
    }
    if (tid < 8) {
        uint32_t sbase = (uint32_t)__cvta_generic_to_shared(smf + SM_SCAL(b));
        CP_ASYNC16(sbase + tid * 16,       &g_f2[h * N_ + j0 + tid * 4]);
        CP_ASYNC16(sbase + 128 + tid * 16, &g_u [h * N_ + j0 + tid * 4]);
        CP_ASYNC16(sbase + 256 + tid * 16, &g_w [h * N_ + j0 + tid * 4]);
    }
    CP_COMMIT();
}

__global__ void __launch_bounds__(256, 2) flash_kernel() {
    extern __shared__ float smf[];

    const int h  = blockIdx.y;
    const int i0 = blockIdx.x * 64;
    const int sp = blockIdx.z;
    const int tid = threadIdx.x;
    const int w = tid >> 5, lane = tid & 31;
    const int gid = lane >> 2, tig = lane & 3;
    const int mw = (w & 3) * 16;          // m-band
    const int ch = (w >> 2) * 16;         // S col-half (16 j cols)
    const int nh2 = (w >> 2) * 32;        // PV d-half (32 dims)
    const int r0 = mw + gid, r1 = r0 + 8;

    const int j0base = sp * 2048;
    prefetch_tile(smf, 0, h, j0base, tid);

    // Q fragments: registers, loaded once (reused for all 64 j-tiles)
    uint32_t qh[8][4], ql[8][4];
    {
        const size_t base0 = ((size_t)h * N_ + i0 + r0) * (2 * M_);
        const size_t base1 = ((size_t)h * N_ + i0 + r1) * (2 * M_);
        #pragma unroll
        for (int kk = 0; kk < 8; kk++) {
            float2 a0 = *(const float2*)&g_adjpx[base0 + 2 * (kk * 8 + tig)];
            float2 a1 = *(const float2*)&g_adjpx[base1 + 2 * (kk * 8 + tig)];
            float2 a2 = *(const float2*)&g_adjpx[base0 + 2 * (kk * 8 + tig + 4)];
            float2 a3 = *(const float2*)&g_adjpx[base1 + 2 * (kk * 8 + tig + 4)];
            qh[kk][0] = FU(a0.x); qh[kk][1] = FU(a1.x); qh[kk][2] = FU(a2.x); qh[kk][3] = FU(a3.x);
            ql[kk][0] = FU(a0.y); ql[kk][1] = FU(a1.y); ql[kk][2] = FU(a2.y); ql[kk][3] = FU(a3.y);
        }
    }
    if (tid < 64) {
        float f1v = g_f1[h * N_ + i0 + tid];
        smf[SM_T + tid] = -f1v;
        smf[SM_R + tid] = __expf(-0.8f * f1v);
        smf[SM_L + tid] = 0.f;
    }
    __syncthreads();
    const float t0 = smf[SM_T + r0], t1 = smf[SM_T + r1];
    const float rr0 = smf[SM_R + r0], rr1 = smf[SM_R + r1];

    float oacc[4][4] = {};
    float l0 = 0.f, l1 = 0.f;
    float* Px = smf + SM_PX;

    for (int it = 0; it < 64; it++) {
        const int b = it & 1;
        float* KTx = smf + SM_KTX(b);
        float* VTx = smf + SM_VTX(b);
        const float* f2s = smf + SM_SCAL(b);
        const float* us = f2s + 32;
        const float* ws = f2s + 64;

        CP_WAIT0();
        __syncthreads();   // buffer b landed; prev iter's use of this buffer done
        if (it < 63) prefetch_tile(smf, 1 - b, h, j0base + (it + 1) * 32, tid);

        // ---- S = Q @ K^T via 3xTF32 mma (Q in regs), 16 cols per warp ----
        float sacc[2][4] = {};
        #pragma unroll
        for (int kk = 0; kk < 8; kk++) {
            const int k0 = kk * 8;
            #pragma unroll
            for (int nb = 0; nb < 2; nb++) {
                const int jc = ch + 8 * nb + gid;
                float2 b0 = *(const float2*)&KTx[jc * TPK_ + 2 * (k0 + tig)];
                float2 b1 = *(const float2*)&KTx[jc * TPK_ + 2 * (k0 + tig + 4)];
                uint32_t Bh[2] = {FU(b0.x), FU(b1.x)};
                uint32_t Bl[2] = {FU(b0.y), FU(b1.y)};
                mma_tf32(sacc[nb], qh[kk], Bh);
                mma_tf32(sacc[nb], qh[kk], Bl);
                mma_tf32(sacc[nb], ql[kk], Bh);
            }
        }

        // ---- factored softmax weights, tf32-quantized (self-consistent l) ----
        #pragma unroll
        for (int nb = 0; nb < 2; nb++) {
            const int cj = ch + 8 * nb + 2 * tig;
            float f2a = f2s[cj], f2b = f2s[cj + 1];
            float ua = us[cj], ub = us[cj + 1];
            float wa = ws[cj], wb = ws[cj + 1];
            float p00 = (sacc[nb][0] > 0.f) ? ((f2a > t0) ? ua : rr0 * wa) : 0.f;
            float p01 = (sacc[nb][1] > 0.f) ? ((f2b > t0) ? ub : rr0 * wb) : 0.f;
            float p10 = (sacc[nb][2] > 0.f) ? ((f2a > t1) ? ua : rr1 * wa) : 0.f;
            float p11 = (sacc[nb][3] > 0.f) ? ((f2b > t1) ? ub : rr1 * wb) : 0.f;
            p00 = tf32round(p00); p01 = tf32round(p01);
            p10 = tf32round(p10); p11 = tf32round(p11);
            l0 += p00 + p01;
            l1 += p10 + p11;
            *(float2*)&Px[r0 * TPP_ + cj] = make_float2(p00, p01);
            *(float2*)&Px[r1 * TPP_ + cj] = make_float2(p10, p11);
        }
        __syncthreads();   // Px visible to all warps

        // ---- O += P @ V via 2 mmas (P exact in tf32; V hi+lo) ----
        #pragma unroll
        for (int kk = 0; kk < 4; kk++) {
            const int k0 = kk * 8;
            float a0 = Px[r0 * TPP_ + k0 + tig];
            float a1 = Px[r1 * TPP_ + k0 + tig];
            float a2 = Px[r0 * TPP_ + k0 + tig + 4];
            float a3 = Px[r1 * TPP_ + k0 + tig + 4];
            uint32_t Ah[4] = {FU(a0), FU(a1), FU(a2), FU(a3)};
            #pragma unroll
            for (int nb = 0; nb < 4; nb++) {
                const int dc = nh2 + 8 * nb + gid;
                float2 b0 = *(const float2*)&VTx[dc * TPV_ + 2 * (k0 + tig)];
                float2 b1 = *(const float2*)&VTx[dc * TPV_ + 2 * (k0 + tig + 4)];
                uint32_t Bh[2] = {FU(b0.x), FU(b1.x)};
                uint32_t Bl[2] = {FU(b0.y), FU(b1.y)};
                mma_tf32(oacc[nb], Ah, Bh);
                mma_tf32(oacc[nb], Ah, Bl);
            }
        }
    }

    // l: reduce within quad (lanes sharing rows), combine across warps in smem
    l0 += __shfl_xor_sync(0xffffffffu, l0, 1);
    l0 += __shfl_xor_sync(0xffffffffu, l0, 2);
    l1 += __shfl_xor_sync(0xffffffffu, l1, 1);
    l1 += __shfl_xor_sync(0xffffffffu, l1, 2);
    if (tig == 0) {
        atomicAdd(&smf[SM_L + r0], l0);
        atomicAdd(&smf[SM_L + r1], l1);
    }
    __syncthreads();

    const int rowb = (sp * H_ + h) * N_ + i0;
    if (tid < 64) g_pl[rowb + tid] = smf[SM_L + tid];

    #pragma unroll
    for (int nb = 0; nb < 4; nb++) {
        const int dc = nh2 + 8 * nb + 2 * tig;
        *(float2*)&g_po[(size_t)(rowb + r0) * D_ + dc] = make_float2(oacc[nb][0], oacc[nb][1]);
        *(float2*)&g_po[(size_t)(rowb + r1) * D_ + dc] = make_float2(oacc[nb][2], oacc[nb][3]);
    }
}

// ---------------------------------------------------------------------------
// K4b: merge the two KV splits, normalize, elu.  One thread per (h,n,d4).
// ---------------------------------------------------------------------------
__global__ void merge_kernel() {
    int idx = blockIdx.x * 256 + threadIdx.x;     // < H*N*16
    int d4 = (idx & 15) * 4;
    int hn = idx >> 4;
    float inv = 1.f / (g_pl[hn] + g_pl[HN_ + hn]);
    float4 o1 = *(const float4*)&g_po[(size_t)hn * D_ + d4];
    float4 o2 = *(const float4*)&g_po[(size_t)(HN_ + hn) * D_ + d4];
    float4 v;
    v.x = (o1.x + o2.x) * inv;
    v.y = (o1.y + o2.y) * inv;
    v.z = (o1.z + o2.z) * inv;
    v.w = (o1.w + o2.w) * inv;
    v.x = (v.x > 0.f) ? v.x : (__expf(v.x) - 1.f);
    v.y = (v.y > 0.f) ? v.y : (__expf(v.y) - 1.f);
    v.z = (v.z > 0.f) ? v.z : (__expf(v.z) - 1.f);
    v.w = (v.w > 0.f) ? v.w : (__expf(v.w) - 1.f);
    *(float4*)&g_head[(size_t)hn * D_ + d4] = v;
}

// ---------------------------------------------------------------------------
// K5: out = leaky( cat(heads) @ Wd + bd ).  Grid N/64, 256 threads.
// ---------------------------------------------------------------------------
__global__ void final_kernel(const float* __restrict__ Wd,
                             const float* __restrict__ bd,
                             float* __restrict__ out) {
    __shared__ float AT[64][68];
    __shared__ float Ws[64][64];
    const int n0 = blockIdx.x * 64;
    const int tid = threadIdx.x;
    const int ty = tid >> 4, tx = tid & 15;

    float acc[4][4] = {};

    for (int h = 0; h < H_; h++) {
        __syncthreads();
        for (int e = tid; e < 64 * 16; e += 256) {
            int r = e >> 4, k4 = (e & 15) * 4;
            float4 a = *(const float4*)&g_head[((size_t)h * N_ + n0 + r) * D_ + k4];
            AT[k4 + 0][r] = a.x;
            AT[k4 + 1][r] = a.y;
            AT[k4 + 2][r] = a.z;
            AT[k4 + 3][r] = a.w;
        }
        for (int e = tid; e < 64 * 16; e += 256) {
            int rr = e >> 4, c4 = (e & 15) * 4;
            *(float4*)&Ws[rr][c4] = *(const float4*)&Wd[(size_t)(h * 64 + rr) * D_ + c4];
        }
        __syncthreads();
        #pragma unroll 8
        for (int k = 0; k < 64; k++) {
            float4 a = *(float4*)&AT[k][4 * ty];
            float4 b = *(float4*)&Ws[k][4 * tx];
            acc[0][0] += a.x * b.x; acc[0][1] += a.x * b.y; acc[0][2] += a.x * b.z; acc[0][3] += a.x * b.w;
            acc[1][0] += a.y * b.x; acc[1][1] += a.y * b.y; acc[1][2] += a.y * b.z; acc[1][3] += a.y * b.w;
            acc[2][0] += a.z * b.x; acc[2][1] += a.z * b.y; acc[2][2] += a.z * b.z; acc[2][3] += a.z * b.w;
            acc[3][0] += a.w * b.x; acc[3][1] += a.w * b.y; acc[3][2] += a.w * b.z; acc[3][3] += a.w * b.w;
        }
    }
    #pragma unroll
    for (int j = 0; j < 4; j++) {
        float b = bd[4 * tx + j];
        #pragma unroll
        for (int i = 0; i < 4; i++) {
            float v = acc[i][j] + b;
            v = (v > 0.f) ? v : SLOPE_ * v;
            out[(size_t)(n0 + 4 * ty + i) * D_ + 4 * tx + j] = v;
        }
    }
}

// ---------------------------------------------------------------------------
extern "C" void kernel_launch(void* const* d_in, const int* in_sizes, int n_in,
                              void* d_out, int out_size) {
    const float* x    = (const float*)d_in[0];
    const float* mask = (const float*)d_in[1];
    const float* adj  = (const float*)d_in[2];
    const float* W    = (const float*)d_in[3];
    const float* a1   = (const float*)d_in[4];
    const float* a2   = (const float*)d_in[5];
    const float* aw   = (const float*)d_in[6];
    const float* Wd   = (const float*)d_in[7];
    const float* bd   = (const float*)d_in[8];
    float* out        = (float*)d_out;

    cudaFuncSetAttribute(flash_kernel,
                         cudaFuncAttributeMaxDynamicSharedMemorySize,
                         SM_FLOATS * (int)sizeof(float));

    wh_kernel<<<dim3(N_ / 64, H_), 256>>>(x, mask, W);
    f12_kernel<<<(H_ * N_) / 8, 256>>>(a1, a2);
    adjp_kernel<<<(N_ * M_) / 8, 256>>>(adj, aw);
    flash_kernel<<<dim3(N_ / 64, H_, 2), 256, SM_FLOATS * (int)sizeof(float)>>>();
    merge_kernel<<<(HN_ * 16) / 256, 256>>>();
    final_kernel<<<N_ / 64, 256>>>(Wd, bd, out);
}

// round 14
// speedup vs baseline: 1.4826x; 1.0193x over previous
#include <cuda_runtime.h>
#include <cstdint>

// ---------------------------------------------------------------------------
// GraphAttentionWithMask: 4-head GAT, N=4096, F=512, D=64, E=128, M=64
//
//  K1 wh_kernel    : Wh = (mask*x) @ W[h];  writes Wh + WhTx (tf32 hi/lo interleaved)
//  K2 f12_kernel   : f1/f2[h][n]; u=exp(f2), w=exp(0.2*f2)
//  K3 adjp_kernel  : adjpx[h][n][2m] = tf32 hi/lo of adj[n][m]·aw[h]
//  K4 flash_kernel : masked attention, factored softmax, tf32-quantized P.
//                    Each warp owns a 16-col j-half end-to-end: S (3xTF32) ->
//                    softmax -> shuffle C->A fragment -> PV (2 mma, all 64 d).
//                    ONE barrier per tile.  Partial-O merge across warp pairs
//                    in epilogue.  cp.async double buffer, 71 KB smem,
//                    2 CTAs/SM, split-KV x2.
//  K4b merge_kernel: (o1+o2)/(l1+l2), elu
//  K5 final_kernel : out = leaky(cat(heads) @ Wd + bd)
// ---------------------------------------------------------------------------

#define N_  4096
#define F_  512
#define D_  64
#define H_  4
#define E_  128
#define M_  64
#define HN_ (H_ * N_)
#define SLOPE_ 0.2f

__device__ __forceinline__ float2 tf32split(float a) {
    uint32_t hb;
    asm("cvt.rna.tf32.f32 %0, %1;" : "=r"(hb) : "f"(a));
    float hf = __uint_as_float(hb);
    return make_float2(hf, a - hf);
}

__device__ __forceinline__ float tf32round(float a) {
    uint32_t hb;
    asm("cvt.rna.tf32.f32 %0, %1;" : "=r"(hb) : "f"(a));
    return __uint_as_float(hb);
}

__device__ __forceinline__ void mma_tf32(float* d, const uint32_t* a, const uint32_t* b) {
    asm volatile(
        "mma.sync.aligned.m16n8k8.row.col.f32.tf32.tf32.f32 "
        "{%0,%1,%2,%3}, {%4,%5,%6,%7}, {%8,%9}, {%0,%1,%2,%3};"
        : "+f"(d[0]), "+f"(d[1]), "+f"(d[2]), "+f"(d[3])
        : "r"(a[0]), "r"(a[1]), "r"(a[2]), "r"(a[3]), "r"(b[0]), "r"(b[1]));
}

#define FU(x) __float_as_uint(x)

#define CP_ASYNC16(smaddr, gptr) \
    asm volatile("cp.async.cg.shared.global [%0], [%1], 16;" \
                 :: "r"(smaddr), "l"(gptr))
#define CP_COMMIT() asm volatile("cp.async.commit_group;")
#define CP_WAIT0()  asm volatile("cp.async.wait_group 0;")

__device__ float g_Wh   [H_ * N_ * D_];
__device__ float g_WhTx [H_ * D_ * 2 * N_];   // [h][d][2n] interleaved hi/lo
__device__ float g_adjpx[H_ * N_ * 2 * M_];   // [h][n][2m] interleaved hi/lo
__device__ float g_f1   [H_ * N_];
__device__ float g_f2   [H_ * N_];
__device__ float g_u    [H_ * N_];            // exp(f2)
__device__ float g_w    [H_ * N_];            // exp(0.2 f2)
__device__ float g_head [H_ * N_ * D_];
__device__ float g_po   [2 * H_ * N_ * D_];   // split-KV partials
__device__ float g_pl   [2 * H_ * N_];

// ---------------------------------------------------------------------------
// K1: Wh = (mask*x) @ W[h].  Grid (N/64, H), 256 threads, 4x4 reg tile.
// ---------------------------------------------------------------------------
__global__ void wh_kernel(const float* __restrict__ x,
                          const float* __restrict__ mask,
                          const float* __restrict__ W) {
    __shared__ float xT[64][68];
    __shared__ float Ws[64][64];
    const int h  = blockIdx.y;
    const int n0 = blockIdx.x * 64;
    const int tid = threadIdx.x;
    const int ty = tid >> 4, tx = tid & 15;

    float acc[4][4] = {};

    for (int f0 = 0; f0 < F_; f0 += 64) {
        __syncthreads();
        for (int e = tid; e < 64 * 16; e += 256) {
            int r = e >> 4, k4 = (e & 15) * 4;
            float mk = mask[n0 + r];
            float4 xv = *(const float4*)&x[(size_t)(n0 + r) * F_ + f0 + k4];
            xT[k4 + 0][r] = xv.x * mk;
            xT[k4 + 1][r] = xv.y * mk;
            xT[k4 + 2][r] = xv.z * mk;
            xT[k4 + 3][r] = xv.w * mk;
        }
        for (int e = tid; e < 64 * 16; e += 256) {
            int rr = e >> 4, c4 = (e & 15) * 4;
            *(float4*)&Ws[rr][c4] =
                *(const float4*)&W[((size_t)h * F_ + f0 + rr) * D_ + c4];
        }
        __syncthreads();
        #pragma unroll 8
        for (int k = 0; k < 64; k++) {
            float4 a = *(float4*)&xT[k][4 * ty];
            float4 b = *(float4*)&Ws[k][4 * tx];
            acc[0][0] += a.x * b.x; acc[0][1] += a.x * b.y; acc[0][2] += a.x * b.z; acc[0][3] += a.x * b.w;
            acc[1][0] += a.y * b.x; acc[1][1] += a.y * b.y; acc[1][2] += a.y * b.z; acc[1][3] += a.y * b.w;
            acc[2][0] += a.z * b.x; acc[2][1] += a.z * b.y; acc[2][2] += a.z * b.z; acc[2][3] += a.z * b.w;
            acc[3][0] += a.w * b.x; acc[3][1] += a.w * b.y; acc[3][2] += a.w * b.z; acc[3][3] += a.w * b.w;
        }
    }
    #pragma unroll
    for (int i = 0; i < 4; i++)
        #pragma unroll
        for (int j = 0; j < 4; j++)
            g_Wh[((size_t)h * N_ + n0 + 4 * ty + i) * D_ + 4 * tx + j] = acc[i][j];
    // transposed hi/lo interleaved copy for flash PV mma (B operand)
    #pragma unroll
    for (int j = 0; j < 4; j++) {
        float2 s0 = tf32split(acc[0][j]);
        float2 s1 = tf32split(acc[1][j]);
        float2 s2 = tf32split(acc[2][j]);
        float2 s3 = tf32split(acc[3][j]);
        size_t base = ((size_t)h * D_ + 4 * tx + j) * (2 * N_) + 2 * (n0 + 4 * ty);
        *(float4*)&g_WhTx[base]     = make_float4(s0.x, s0.y, s1.x, s1.y);
        *(float4*)&g_WhTx[base + 4] = make_float4(s2.x, s2.y, s3.x, s3.y);
    }
}

// ---------------------------------------------------------------------------
// K2: f1/f2 = Wh @ a1/a2; u = exp(f2), w = exp(0.2 f2).  One warp per (h,n).
// ---------------------------------------------------------------------------
__global__ void f12_kernel(const float* __restrict__ a1,
                           const float* __restrict__ a2) {
    int w = (blockIdx.x * blockDim.x + threadIdx.x) >> 5;
    int lane = threadIdx.x & 31;
    int h = w / N_, n = w % N_;
    const float2 v  = ((const float2*)&g_Wh[((size_t)h * N_ + n) * D_])[lane];
    const float2 w1 = ((const float2*)&a1[h * D_])[lane];
    const float2 w2 = ((const float2*)&a2[h * D_])[lane];
    float s1 = v.x * w1.x + v.y * w1.y;
    float s2 = v.x * w2.x + v.y * w2.y;
    #pragma unroll
    for (int off = 16; off; off >>= 1) {
        s1 += __shfl_xor_sync(0xffffffffu, s1, off);
        s2 += __shfl_xor_sync(0xffffffffu, s2, off);
    }
    if (lane == 0) {
        g_f1[h * N_ + n] = s1;
        g_f2[h * N_ + n] = s2;
        g_u [h * N_ + n] = __expf(s2);
        g_w [h * N_ + n] = __expf(0.2f * s2);
    }
}

// ---------------------------------------------------------------------------
// K3: adjpx[h][n][2m] = tf32 hi/lo of adj[n][m]·aw[h].  One warp per (n,m).
// ---------------------------------------------------------------------------
__global__ void adjp_kernel(const float* __restrict__ adj,
                            const float* __restrict__ aw) {
    __shared__ float aws[H_ * E_];
    int tid = threadIdx.x;
    if (tid < H_ * E_) aws[tid] = aw[tid];
    if (tid + 256 < H_ * E_) aws[tid + 256] = aw[tid + 256];
    __syncthreads();

    int w = (blockIdx.x * blockDim.x + tid) >> 5;   // 0..N*M-1
    int lane = tid & 31;
    int n = w / M_, m = w % M_;
    float4 v = ((const float4*)&adj[(size_t)(n * M_ + m) * E_])[lane];
    float s[H_];
    #pragma unroll
    for (int h = 0; h < H_; h++) {
        const float4 aw4 = ((const float4*)&aws[h * E_])[lane];
        s[h] = v.x * aw4.x + v.y * aw4.y + v.z * aw4.z + v.w * aw4.w;
    }
    #pragma unroll
    for (int off = 16; off; off >>= 1) {
        #pragma unroll
        for (int h = 0; h < H_; h++)
            s[h] += __shfl_xor_sync(0xffffffffu, s[h], off);
    }
    if (lane == 0) {
        #pragma unroll
        for (int h = 0; h < H_; h++) {
            float2 sp = tf32split(s[h]);
            *(float2*)&g_adjpx[((size_t)h * N_ + n) * (2 * M_) + 2 * m] = sp;
        }
    }
}

// ---------------------------------------------------------------------------
// K4: flash attention, warp-private j-halves, ONE barrier per tile.
// Grid (N/64, H, 2), 256 threads = 8 warps.
// Warp w: m-band (w&3)*16, j col-half (w>>2)*16; PV covers all 64 dims.
// ---------------------------------------------------------------------------
#define TPK_ 136   // K tile pitch: 32 rows x (2*64 + 8)
#define TPV_ 68    // V tile pitch: 64 rows x (2*32 + 4)
#define SM_KTX(b)  ((b) * 32 * TPK_)
#define SM_VTX(b)  (2 * 32 * TPK_ + (b) * 64 * TPV_)
#define SM_SCAL(b) (2 * 32 * TPK_ + 2 * 64 * TPV_ + (b) * 96)
#define SM_T       (2 * 32 * TPK_ + 2 * 64 * TPV_ + 192)
#define SM_R       (SM_T + 64)
#define SM_L       (SM_R + 64)
#define SM_FLOATS  (SM_L + 64)

__device__ __forceinline__ void prefetch_tile(float* smf, int b, int h, int j0, int tid) {
    uint32_t kbase = (uint32_t)__cvta_generic_to_shared(smf + SM_KTX(b));
    uint32_t vbase = (uint32_t)__cvta_generic_to_shared(smf + SM_VTX(b));
    #pragma unroll
    for (int e = tid; e < 32 * 32; e += 256) {   // K: 32 rows x 32 chunks
        int r = e >> 5, c4 = (e & 31) * 4;
        CP_ASYNC16(kbase + (uint32_t)(r * TPK_ + c4) * 4,
                   &g_adjpx[((size_t)h * N_ + j0 + r) * (2 * M_) + c4]);
    }
    #pragma unroll
    for (int e = tid; e < 64 * 16; e += 256) {   // V: 64 rows x 16 chunks
        int r = e >> 4, c4 = (e & 15) * 4;
        CP_ASYNC16(vbase + (uint32_t)(r * TPV_ + c4) * 4,
                   &g_WhTx[((size_t)h * D_ + r) * (2 * N_) + 2 * j0 + c4]);
    }
    if (tid < 8) {
        uint32_t sbase = (uint32_t)__cvta_generic_to_shared(smf + SM_SCAL(b));
        CP_ASYNC16(sbase + tid * 16,       &g_f2[h * N_ + j0 + tid * 4]);
        CP_ASYNC16(sbase + 128 + tid * 16, &g_u [h * N_ + j0 + tid * 4]);
        CP_ASYNC16(sbase + 256 + tid * 16, &g_w [h * N_ + j0 + tid * 4]);
    }
    CP_COMMIT();
}

__global__ void __launch_bounds__(256, 2) flash_kernel() {
    extern __shared__ float smf[];

    const int h  = blockIdx.y;
    const int i0 = blockIdx.x * 64;
    const int sp = blockIdx.z;
    const int tid = threadIdx.x;
    const int w = tid >> 5, lane = tid & 31;
    const int gid = lane >> 2, tig = lane & 3;
    const int mw = (w & 3) * 16;          // m-band
    const int ch = (w >> 2) * 16;         // j col-half (16 cols of each tile)
    const int r0 = mw + gid, r1 = r0 + 8;

    const int j0base = sp * 2048;
    prefetch_tile(smf, 0, h, j0base, tid);

    // Q fragments: registers, loaded once (reused for all 64 j-tiles)
    uint32_t qh[8][4], ql[8][4];
    {
        const size_t base0 = ((size_t)h * N_ + i0 + r0) * (2 * M_);
        const size_t base1 = ((size_t)h * N_ + i0 + r1) * (2 * M_);
        #pragma unroll
        for (int kk = 0; kk < 8; kk++) {
            float2 a0 = *(const float2*)&g_adjpx[base0 + 2 * (kk * 8 + tig)];
            float2 a1 = *(const float2*)&g_adjpx[base1 + 2 * (kk * 8 + tig)];
            float2 a2 = *(const float2*)&g_adjpx[base0 + 2 * (kk * 8 + tig + 4)];
            float2 a3 = *(const float2*)&g_adjpx[base1 + 2 * (kk * 8 + tig + 4)];
            qh[kk][0] = FU(a0.x); qh[kk][1] = FU(a1.x); qh[kk][2] = FU(a2.x); qh[kk][3] = FU(a3.x);
            ql[kk][0] = FU(a0.y); ql[kk][1] = FU(a1.y); ql[kk][2] = FU(a2.y); ql[kk][3] = FU(a3.y);
        }
    }
    if (tid < 64) {
        float f1v = g_f1[h * N_ + i0 + tid];
        smf[SM_T + tid] = -f1v;
        smf[SM_R + tid] = __expf(-0.8f * f1v);
        smf[SM_L + tid] = 0.f;
    }
    __syncthreads();
    const float t0 = smf[SM_T + r0], t1 = smf[SM_T + r1];
    const float rr0 = smf[SM_R + r0], rr1 = smf[SM_R + r1];

    float oacc[8][4] = {};     // all 64 dims (8 n-blocks), warp's j-half only
    float l0 = 0.f, l1 = 0.f;

    for (int it = 0; it < 64; it++) {
        const int b = it & 1;
        float* KTx = smf + SM_KTX(b);
        float* VTx = smf + SM_VTX(b);
        const float* f2s = smf + SM_SCAL(b);
        const float* us = f2s + 32;
        const float* ws = f2s + 64;

        CP_WAIT0();
        __syncthreads();   // buffer b landed for all; prev iter fully finished
        if (it < 63) prefetch_tile(smf, 1 - b, h, j0base + (it + 1) * 32, tid);

        // ---- S = Q @ K^T via 3xTF32 mma (Q in regs), 16 cols per warp ----
        float sacc[2][4] = {};
        #pragma unroll
        for (int kk = 0; kk < 8; kk++) {
            const int k0 = kk * 8;
            #pragma unroll
            for (int nb = 0; nb < 2; nb++) {
                const int jc = ch + 8 * nb + gid;
                float2 b0 = *(const float2*)&KTx[jc * TPK_ + 2 * (k0 + tig)];
                float2 b1 = *(const float2*)&KTx[jc * TPK_ + 2 * (k0 + tig + 4)];
                uint32_t Bh[2] = {FU(b0.x), FU(b1.x)};
                uint32_t Bl[2] = {FU(b0.y), FU(b1.y)};
                mma_tf32(sacc[nb], qh[kk], Bh);
                mma_tf32(sacc[nb], qh[kk], Bl);
                mma_tf32(sacc[nb], ql[kk], Bh);
            }
        }

        // ---- factored softmax weights, tf32-quantized (self-consistent l) ----
        float p[2][4];
        #pragma unroll
        for (int nb = 0; nb < 2; nb++) {
            const int cj = ch + 8 * nb + 2 * tig;
            float f2a = f2s[cj], f2b = f2s[cj + 1];
            float ua = us[cj], ub = us[cj + 1];
            float wa = ws[cj], wb = ws[cj + 1];
            float p00 = (sacc[nb][0] > 0.f) ? ((f2a > t0) ? ua : rr0 * wa) : 0.f;
            float p01 = (sacc[nb][1] > 0.f) ? ((f2b > t0) ? ub : rr0 * wb) : 0.f;
            float p10 = (sacc[nb][2] > 0.f) ? ((f2a > t1) ? ua : rr1 * wa) : 0.f;
            float p11 = (sacc[nb][3] > 0.f) ? ((f2b > t1) ? ub : rr1 * wb) : 0.f;
            p00 = tf32round(p00); p01 = tf32round(p01);
            p10 = tf32round(p10); p11 = tf32round(p11);
            l0 += p00 + p01;
            l1 += p10 + p11;
            p[nb][0] = p00; p[nb][1] = p01; p[nb][2] = p10; p[nb][3] = p11;
        }

        // ---- C->A fragment conversion via shuffles, then PV (2 mma) ----
        // Value at (row, local col c) lives in lane 4*gid + ((c&7)>>1),
        // register p[c>>3][(c&1) + 2*(row==r1)].
        #pragma unroll
        for (int kk = 0; kk < 2; kk++) {
            const int srcA = 4 * gid + (tig >> 1);
            const int srcB = srcA + 2;
            float v0a = __shfl_sync(0xffffffffu, p[kk][0], srcA);
            float v0b = __shfl_sync(0xffffffffu, p[kk][1], srcA);
            float v1a = __shfl_sync(0xffffffffu, p[kk][2], srcA);
            float v1b = __shfl_sync(0xffffffffu, p[kk][3], srcA);
            float v2a = __shfl_sync(0xffffffffu, p[kk][0], srcB);
            float v2b = __shfl_sync(0xffffffffu, p[kk][1], srcB);
            float v3a = __shfl_sync(0xffffffffu, p[kk][2], srcB);
            float v3b = __shfl_sync(0xffffffffu, p[kk][3], srcB);
            const bool odd = (tig & 1);
            uint32_t Ah[4];
            Ah[0] = FU(odd ? v0b : v0a);   // (r0, 8kk+tig)
            Ah[1] = FU(odd ? v1b : v1a);   // (r1, 8kk+tig)
            Ah[2] = FU(odd ? v2b : v2a);   // (r0, 8kk+tig+4)
            Ah[3] = FU(odd ? v3b : v3a);   // (r1, 8kk+tig+4)
            #pragma unroll
            for (int nb = 0; nb < 8; nb++) {
                const int dc = 8 * nb + gid;
                float2 b0 = *(const float2*)&VTx[dc * TPV_ + 2 * (ch + 8 * kk + tig)];
                float2 b1 = *(const float2*)&VTx[dc * TPV_ + 2 * (ch + 8 * kk + tig + 4)];
                uint32_t Bh[2] = {FU(b0.x), FU(b1.x)};
                uint32_t Bl[2] = {FU(b0.y), FU(b1.y)};
                mma_tf32(oacc[nb], Ah, Bh);
                mma_tf32(oacc[nb], Ah, Bl);
            }
        }
    }

    // l: reduce within quad, combine across warps in smem
    l0 += __shfl_xor_sync(0xffffffffu, l0, 1);
    l0 += __shfl_xor_sync(0xffffffffu, l0, 2);
    l1 += __shfl_xor_sync(0xffffffffu, l1, 1);
    l1 += __shfl_xor_sync(0xffffffffu, l1, 2);
    if (tig == 0) {
        atomicAdd(&smf[SM_L + r0], l0);
        atomicAdd(&smf[SM_L + r1], l1);
    }
    __syncthreads();   // everyone out of the loop; VTx(0) now free as scratch

    // merge partial O across col-half warp pairs (w and w+4 share m-band)
    float* scratch = smf + SM_VTX(0);   // 64 rows x pitch 68 (fits in V buffer)
    if (w >= 4) {
        #pragma unroll
        for (int nb = 0; nb < 8; nb++) {
            const int dc = 8 * nb + 2 * tig;
            *(float2*)&scratch[r0 * 68 + dc] = make_float2(oacc[nb][0], oacc[nb][1]);
            *(float2*)&scratch[r1 * 68 + dc] = make_float2(oacc[nb][2], oacc[nb][3]);
        }
    }
    __syncthreads();

    const int rowb = (sp * H_ + h) * N_ + i0;
    if (tid < 64) g_pl[rowb + tid] = smf[SM_L + tid];

    if (w < 4) {
        #pragma unroll
        for (int nb = 0; nb < 8; nb++) {
            const int dc = 8 * nb + 2 * tig;
            float2 s0v = *(const float2*)&scratch[r0 * 68 + dc];
            float2 s1v = *(const float2*)&scratch[r1 * 68 + dc];
            *(float2*)&g_po[(size_t)(rowb + r0) * D_ + dc] =
                make_float2(oacc[nb][0] + s0v.x, oacc[nb][1] + s0v.y);
            *(float2*)&g_po[(size_t)(rowb + r1) * D_ + dc] =
                make_float2(oacc[nb][2] + s1v.x, oacc[nb][3] + s1v.y);
        }
    }
}

// ---------------------------------------------------------------------------
// K4b: merge the two KV splits, normalize, elu.  One thread per (h,n,d4).
// ---------------------------------------------------------------------------
__global__ void merge_kernel() {
    int idx = blockIdx.x * 256 + threadIdx.x;     // < H*N*16
    int d4 = (idx & 15) * 4;
    int hn = idx >> 4;
    float inv = 1.f / (g_pl[hn] + g_pl[HN_ + hn]);
    float4 o1 = *(const float4*)&g_po[(size_t)hn * D_ + d4];
    float4 o2 = *(const float4*)&g_po[(size_t)(HN_ + hn) * D_ + d4];
    float4 v;
    v.x = (o1.x + o2.x) * inv;
    v.y = (o1.y + o2.y) * inv;
    v.z = (o1.z + o2.z) * inv;
    v.w = (o1.w + o2.w) * inv;
    v.x = (v.x > 0.f) ? v.x : (__expf(v.x) - 1.f);
    v.y = (v.y > 0.f) ? v.y : (__expf(v.y) - 1.f);
    v.z = (v.z > 0.f) ? v.z : (__expf(v.z) - 1.f);
    v.w = (v.w > 0.f) ? v.w : (__expf(v.w) - 1.f);
    *(float4*)&g_head[(size_t)hn * D_ + d4] = v;
}

// ---------------------------------------------------------------------------
// K5: out = leaky( cat(heads) @ Wd + bd ).  Grid N/64, 256 threads.
// ---------------------------------------------------------------------------
__global__ void final_kernel(const float* __restrict__ Wd,
                             const float* __restrict__ bd,
                             float* __restrict__ out) {
    __shared__ float AT[64][68];
    __shared__ float Ws[64][64];
    const int n0 = blockIdx.x * 64;
    const int tid = threadIdx.x;
    const int ty = tid >> 4, tx = tid & 15;

    float acc[4][4] = {};

    for (int h = 0; h < H_; h++) {
        __syncthreads();
        for (int e = tid; e < 64 * 16; e += 256) {
            int r = e >> 4, k4 = (e & 15) * 4;
            float4 a = *(const float4*)&g_head[((size_t)h * N_ + n0 + r) * D_ + k4];
            AT[k4 + 0][r] = a.x;
            AT[k4 + 1][r] = a.y;
            AT[k4 + 2][r] = a.z;
            AT[k4 + 3][r] = a.w;
        }
        for (int e = tid; e < 64 * 16; e += 256) {
            int rr = e >> 4, c4 = (e & 15) * 4;
            *(float4*)&Ws[rr][c4] = *(const float4*)&Wd[(size_t)(h * 64 + rr) * D_ + c4];
        }
        __syncthreads();
        #pragma unroll 8
        for (int k = 0; k < 64; k++) {
            float4 a = *(float4*)&AT[k][4 * ty];
            float4 b = *(float4*)&Ws[k][4 * tx];
            acc[0][0] += a.x * b.x; acc[0][1] += a.x * b.y; acc[0][2] += a.x * b.z; acc[0][3] += a.x * b.w;
            acc[1][0] += a.y * b.x; acc[1][1] += a.y * b.y; acc[1][2] += a.y * b.z; acc[1][3] += a.y * b.w;
            acc[2][0] += a.z * b.x; acc[2][1] += a.z * b.y; acc[2][2] += a.z * b.z; acc[2][3] += a.z * b.w;
            acc[3][0] += a.w * b.x; acc[3][1] += a.w * b.y; acc[3][2] += a.w * b.z; acc[3][3] += a.w * b.w;
        }
    }
    #pragma unroll
    for (int j = 0; j < 4; j++) {
        float b = bd[4 * tx + j];
        #pragma unroll
        for (int i = 0; i < 4; i++) {
            float v = acc[i][j] + b;
            v = (v > 0.f) ? v : SLOPE_ * v;
            out[(size_t)(n0 + 4 * ty + i) * D_ + 4 * tx + j] = v;
        }
    }
}

// ---------------------------------------------------------------------------
extern "C" void kernel_launch(void* const* d_in, const int* in_sizes, int n_in,
                              void* d_out, int out_size) {
    const float* x    = (const float*)d_in[0];
    const float* mask = (const float*)d_in[1];
    const float* adj  = (const float*)d_in[2];
    const float* W    = (const float*)d_in[3];
    const float* a1   = (const float*)d_in[4];
    const float* a2   = (const float*)d_in[5];
    const float* aw   = (const float*)d_in[6];
    const float* Wd   = (const float*)d_in[7];
    const float* bd   = (const float*)d_in[8];
    float* out        = (float*)d_out;

    cudaFuncSetAttribute(flash_kernel,
                         cudaFuncAttributeMaxDynamicSharedMemorySize,
                         SM_FLOATS * (int)sizeof(float));

    wh_kernel<<<dim3(N_ / 64, H_), 256>>>(x, mask, W);
    f12_kernel<<<(H_ * N_) / 8, 256>>>(a1, a2);
    adjp_kernel<<<(N_ * M_) / 8, 256>>>(adj, aw);
    flash_kernel<<<dim3(N_ / 64, H_, 2), 256, SM_FLOATS * (int)sizeof(float)>>>();
    merge_kernel<<<(HN_ * 16) / 256, 256>>>();
    final_kernel<<<N_ / 64, 256>>>(Wd, bd, out);
}

// round 15
// speedup vs baseline: 1.4898x; 1.0049x over previous
#include <cuda_runtime.h>
#include <cstdint>

// ---------------------------------------------------------------------------
// GraphAttentionWithMask: 4-head GAT, N=4096, F=512, D=64, E=128, M=64
//
//  K1 wh_kernel    : Wh = (mask*x) @ W[h];  writes Wh + WhTx (tf32 hi/lo interleaved)
//  K2 f12_kernel   : f1/f2[h][n]; u=exp(f2), w=exp(0.2*f2)
//  K3 adjp_kernel  : adjpx[h][n][2m] = tf32 hi/lo of adj[n][m]·aw[h]
//  K4 flash_kernel : masked attention, factored softmax, tf32-quantized P.
//                    Each warp owns a 16-col j-half end-to-end: S (3xTF32) ->
//                    softmax -> shuffle C->A fragment -> PV (2 mma, all 64 d).
//                    ONE barrier per tile.  Partial-O merge across warp pairs
//                    in epilogue.  cp.async double buffer, 71 KB smem,
//                    2 CTAs/SM, split-KV x2.
//  K4b merge_kernel: (o1+o2)/(l1+l2), elu
//  K5 final_kernel : out = leaky(cat(heads) @ Wd + bd)
// ---------------------------------------------------------------------------

#define N_  4096
#define F_  512
#define D_  64
#define H_  4
#define E_  128
#define M_  64
#define HN_ (H_ * N_)
#define SLOPE_ 0.2f

__device__ __forceinline__ float2 tf32split(float a) {
    uint32_t hb;
    asm("cvt.rna.tf32.f32 %0, %1;" : "=r"(hb) : "f"(a));
    float hf = __uint_as_float(hb);
    return make_float2(hf, a - hf);
}

__device__ __forceinline__ float tf32round(float a) {
    uint32_t hb;
    asm("cvt.rna.tf32.f32 %0, %1;" : "=r"(hb) : "f"(a));
    return __uint_as_float(hb);
}

__device__ __forceinline__ void mma_tf32(float* d, const uint32_t* a, const uint32_t* b) {
    asm volatile(
        "mma.sync.aligned.m16n8k8.row.col.f32.tf32.tf32.f32 "
        "{%0,%1,%2,%3}, {%4,%5,%6,%7}, {%8,%9}, {%0,%1,%2,%3};"
        : "+f"(d[0]), "+f"(d[1]), "+f"(d[2]), "+f"(d[3])
        : "r"(a[0]), "r"(a[1]), "r"(a[2]), "r"(a[3]), "r"(b[0]), "r"(b[1]));
}

#define FU(x) __float_as_uint(x)

#define CP_ASYNC16(smaddr, gptr) \
    asm volatile("cp.async.cg.shared.global [%0], [%1], 16;" \
                 :: "r"(smaddr), "l"(gptr))
#define CP_COMMIT() asm volatile("cp.async.commit_group;")
#define CP_WAIT0()  asm volatile("cp.async.wait_group 0;")

__device__ float g_Wh   [H_ * N_ * D_];
__device__ float g_WhTx [H_ * D_ * 2 * N_];   // [h][d][2n] interleaved hi/lo
__device__ float g_adjpx[H_ * N_ * 2 * M_];   // [h][n][2m] interleaved hi/lo
__device__ float g_f1   [H_ * N_];
__device__ float g_f2   [H_ * N_];
__device__ float g_u    [H_ * N_];            // exp(f2)
__device__ float g_w    [H_ * N_];            // exp(0.2 f2)
__device__ float g_head [H_ * N_ * D_];
__device__ float g_po   [2 * H_ * N_ * D_];   // split-KV partials
__device__ float g_pl   [2 * H_ * N_];

// ---------------------------------------------------------------------------
// K1: Wh = (mask*x) @ W[h].  Grid (N/64, H), 256 threads, 4x4 reg tile.
// ---------------------------------------------------------------------------
__global__ void wh_kernel(const float* __restrict__ x,
                          const float* __restrict__ mask,
                          const float* __restrict__ W) {
    __shared__ float xT[64][68];
    __shared__ float Ws[64][64];
    const int h  = blockIdx.y;
    const int n0 = blockIdx.x * 64;
    const int tid = threadIdx.x;
    const int ty = tid >> 4, tx = tid & 15;

    float acc[4][4] = {};

    for (int f0 = 0; f0 < F_; f0 += 64) {
        __syncthreads();
        for (int e = tid; e < 64 * 16; e += 256) {
            int r = e >> 4, k4 = (e & 15) * 4;
            float mk = mask[n0 + r];
            float4 xv = *(const float4*)&x[(size_t)(n0 + r) * F_ + f0 + k4];
            xT[k4 + 0][r] = xv.x * mk;
            xT[k4 + 1][r] = xv.y * mk;
            xT[k4 + 2][r] = xv.z * mk;
            xT[k4 + 3][r] = xv.w * mk;
        }
        for (int e = tid; e < 64 * 16; e += 256) {
            int rr = e >> 4, c4 = (e & 15) * 4;
            *(float4*)&Ws[rr][c4] =
                *(const float4*)&W[((size_t)h * F_ + f0 + rr) * D_ + c4];
        }
        __syncthreads();
        #pragma unroll 8
        for (int k = 0; k < 64; k++) {
            float4 a = *(float4*)&xT[k][4 * ty];
            float4 b = *(float4*)&Ws[k][4 * tx];
            acc[0][0] += a.x * b.x; acc[0][1] += a.x * b.y; acc[0][2] += a.x * b.z; acc[0][3] += a.x * b.w;
            acc[1][0] += a.y * b.x; acc[1][1] += a.y * b.y; acc[1][2] += a.y * b.z; acc[1][3] += a.y * b.w;
            acc[2][0] += a.z * b.x; acc[2][1] += a.z * b.y; acc[2][2] += a.z * b.z; acc[2][3] += a.z * b.w;
            acc[3][0] += a.w * b.x; acc[3][1] += a.w * b.y; acc[3][2] += a.w * b.z; acc[3][3] += a.w * b.w;
        }
    }
    #pragma unroll
    for (int i = 0; i < 4; i++)
        #pragma unroll
        for (int j = 0; j < 4; j++)
            g_Wh[((size_t)h * N_ + n0 + 4 * ty + i) * D_ + 4 * tx + j] = acc[i][j];
    // transposed hi/lo interleaved copy for flash PV mma (B operand)
    #pragma unroll
    for (int j = 0; j < 4; j++) {
        float2 s0 = tf32split(acc[0][j]);
        float2 s1 = tf32split(acc[1][j]);
        float2 s2 = tf32split(acc[2][j]);
        float2 s3 = tf32split(acc[3][j]);
        size_t base = ((size_t)h * D_ + 4 * tx + j) * (2 * N_) + 2 * (n0 + 4 * ty);
        *(float4*)&g_WhTx[base]     = make_float4(s0.x, s0.y, s1.x, s1.y);
        *(float4*)&g_WhTx[base + 4] = make_float4(s2.x, s2.y, s3.x, s3.y);
    }
}

// ---------------------------------------------------------------------------
// K2: f1/f2 = Wh @ a1/a2; u = exp(f2), w = exp(0.2 f2).  One warp per (h,n).
// ---------------------------------------------------------------------------
__global__ void f12_kernel(const float* __restrict__ a1,
                           const float* __restrict__ a2) {
    int w = (blockIdx.x * blockDim.x + threadIdx.x) >> 5;
    int lane = threadIdx.x & 31;
    int h = w / N_, n = w % N_;
    const float2 v  = ((const float2*)&g_Wh[((size_t)h * N_ + n) * D_])[lane];
    const float2 w1 = ((const float2*)&a1[h * D_])[lane];
    const float2 w2 = ((const float2*)&a2[h * D_])[lane];
    float s1 = v.x * w1.x + v.y * w1.y;
    float s2 = v.x * w2.x + v.y * w2.y;
    #pragma unroll
    for (int off = 16; off; off >>= 1) {
        s1 += __shfl_xor_sync(0xffffffffu, s1, off);
        s2 += __shfl_xor_sync(0xffffffffu, s2, off);
    }
    if (lane == 0) {
        g_f1[h * N_ + n] = s1;
        g_f2[h * N_ + n] = s2;
        g_u [h * N_ + n] = __expf(s2);
        g_w [h * N_ + n] = __expf(0.2f * s2);
    }
}

// ---------------------------------------------------------------------------
// K3: adjpx[h][n][2m] = tf32 hi/lo of adj[n][m]·aw[h].  One warp per (n,m).
// ---------------------------------------------------------------------------
__global__ void adjp_kernel(const float* __restrict__ adj,
                            const float* __restrict__ aw) {
    __shared__ float aws[H_ * E_];
    int tid = threadIdx.x;
    if (tid < H_ * E_) aws[tid] = aw[tid];
    if (tid + 256 < H_ * E_) aws[tid + 256] = aw[tid + 256];
    __syncthreads();

    int w = (blockIdx.x * blockDim.x + tid) >> 5;   // 0..N*M-1
    int lane = tid & 31;
    int n = w / M_, m = w % M_;
    float4 v = ((const float4*)&adj[(size_t)(n * M_ + m) * E_])[lane];
    float s[H_];
    #pragma unroll
    for (int h = 0; h < H_; h++) {
        const float4 aw4 = ((const float4*)&aws[h * E_])[lane];
        s[h] = v.x * aw4.x + v.y * aw4.y + v.z * aw4.z + v.w * aw4.w;
    }
    #pragma unroll
    for (int off = 16; off; off >>= 1) {
        #pragma unroll
        for (int h = 0; h < H_; h++)
            s[h] += __shfl_xor_sync(0xffffffffu, s[h], off);
    }
    if (lane == 0) {
        #pragma unroll
        for (int h = 0; h < H_; h++) {
            float2 sp = tf32split(s[h]);
            *(float2*)&g_adjpx[((size_t)h * N_ + n) * (2 * M_) + 2 * m] = sp;
        }
    }
}

// ---------------------------------------------------------------------------
// K4: flash attention, warp-private j-halves, ONE barrier per tile.
// Grid (N/64, H, 2), 256 threads = 8 warps.
// Warp w: m-band (w&3)*16, j col-half (w>>2)*16; PV covers all 64 dims.
// ---------------------------------------------------------------------------
#define TPK_ 136   // K tile pitch: 32 rows x (2*64 + 8)
#define TPV_ 68    // V tile pitch: 64 rows x (2*32 + 4)
#define SM_KTX(b)  ((b) * 32 * TPK_)
#define SM_VTX(b)  (2 * 32 * TPK_ + (b) * 64 * TPV_)
#define SM_SCAL(b) (2 * 32 * TPK_ + 2 * 64 * TPV_ + (b) * 96)
#define SM_T       (2 * 32 * TPK_ + 2 * 64 * TPV_ + 192)
#define SM_R       (SM_T + 64)
#define SM_L       (SM_R + 64)
#define SM_FLOATS  (SM_L + 64)

__device__ __forceinline__ void prefetch_tile(float* smf, int b, int h, int j0, int tid) {
    uint32_t kbase = (uint32_t)__cvta_generic_to_shared(smf + SM_KTX(b));
    uint32_t vbase = (uint32_t)__cvta_generic_to_shared(smf + SM_VTX(b));
    #pragma unroll
    for (int e = tid; e < 32 * 32; e += 256) {   // K: 32 rows x 32 chunks
        int r = e >> 5, c4 = (e & 31) * 4;
        CP_ASYNC16(kbase + (uint32_t)(r * TPK_ + c4) * 4,
                   &g_adjpx[((size_t)h * N_ + j0 + r) * (2 * M_) + c4]);
    }
    #pragma unroll
    for (int e = tid; e < 64 * 16; e += 256) {   // V: 64 rows x 16 chunks
        int r = e >> 4, c4 = (e & 15) * 4;
        CP_ASYNC16(vbase + (uint32_t)(r * TPV_ + c4) * 4,
                   &g_WhTx[((size_t)h * D_ + r) * (2 * N_) + 2 * j0 + c4]);
    }
    if (tid < 8) {
        uint32_t sbase = (uint32_t)__cvta_generic_to_shared(smf + SM_SCAL(b));
        CP_ASYNC16(sbase + tid * 16,       &g_f2[h * N_ + j0 + tid * 4]);
        CP_ASYNC16(sbase + 128 + tid * 16, &g_u [h * N_ + j0 + tid * 4]);
        CP_ASYNC16(sbase + 256 + tid * 16, &g_w [h * N_ + j0 + tid * 4]);
    }
    CP_COMMIT();
}

__global__ void __launch_bounds__(256, 2) flash_kernel() {
    extern __shared__ float smf[];

    const int h  = blockIdx.y;
    const int i0 = blockIdx.x * 64;
    const int sp = blockIdx.z;
    const int tid = threadIdx.x;
    const int w = tid >> 5, lane = tid & 31;
    const int gid = lane >> 2, tig = lane & 3;
    const int mw = (w & 3) * 16;          // m-band
    const int ch = (w >> 2) * 16;         // j col-half (16 cols of each tile)
    const int r0 = mw + gid, r1 = r0 + 8;

    const int j0base = sp * 2048;
    prefetch_tile(smf, 0, h, j0base, tid);

    // Q fragments: registers, loaded once (reused for all 64 j-tiles)
    uint32_t qh[8][4], ql[8][4];
    {
        const size_t base0 = ((size_t)h * N_ + i0 + r0) * (2 * M_);
        const size_t base1 = ((size_t)h * N_ + i0 + r1) * (2 * M_);
        #pragma unroll
        for (int kk = 0; kk < 8; kk++) {
            float2 a0 = *(const float2*)&g_adjpx[base0 + 2 * (kk * 8 + tig)];
            float2 a1 = *(const float2*)&g_adjpx[base1 + 2 * (kk * 8 + tig)];
            float2 a2 = *(const float2*)&g_adjpx[base0 + 2 * (kk * 8 + tig + 4)];
            float2 a3 = *(const float2*)&g_adjpx[base1 + 2 * (kk * 8 + tig + 4)];
            qh[kk][0] = FU(a0.x); qh[kk][1] = FU(a1.x); qh[kk][2] = FU(a2.x); qh[kk][3] = FU(a3.x);
            ql[kk][0] = FU(a0.y); ql[kk][1] = FU(a1.y); ql[kk][2] = FU(a2.y); ql[kk][3] = FU(a3.y);
        }
    }
    if (tid < 64) {
        float f1v = g_f1[h * N_ + i0 + tid];
        smf[SM_T + tid] = -f1v;
        smf[SM_R + tid] = __expf(-0.8f * f1v);
        smf[SM_L + tid] = 0.f;
    }
    __syncthreads();
    const float t0 = smf[SM_T + r0], t1 = smf[SM_T + r1];
    const float rr0 = smf[SM_R + r0], rr1 = smf[SM_R + r1];

    float oacc[8][4] = {};     // all 64 dims (8 n-blocks), warp's j-half only
    float l0 = 0.f, l1 = 0.f;

    for (int it = 0; it < 64; it++) {
        const int b = it & 1;
        float* KTx = smf + SM_KTX(b);
        float* VTx = smf + SM_VTX(b);
        const float* f2s = smf + SM_SCAL(b);
        const float* us = f2s + 32;
        const float* ws = f2s + 64;

        CP_WAIT0();
        __syncthreads();   // buffer b landed for all; prev iter fully finished
        if (it < 63) prefetch_tile(smf, 1 - b, h, j0base + (it + 1) * 32, tid);

        // ---- S = Q @ K^T via 3xTF32 mma (Q in regs), 16 cols per warp ----
        float sacc[2][4] = {};
        #pragma unroll
        for (int kk = 0; kk < 8; kk++) {
            const int k0 = kk * 8;
            #pragma unroll
            for (int nb = 0; nb < 2; nb++) {
                const int jc = ch + 8 * nb + gid;
                float2 b0 = *(const float2*)&KTx[jc * TPK_ + 2 * (k0 + tig)];
                float2 b1 = *(const float2*)&KTx[jc * TPK_ + 2 * (k0 + tig + 4)];
                uint32_t Bh[2] = {FU(b0.x), FU(b1.x)};
                uint32_t Bl[2] = {FU(b0.y), FU(b1.y)};
                mma_tf32(sacc[nb], qh[kk], Bh);
                mma_tf32(sacc[nb], qh[kk], Bl);
                mma_tf32(sacc[nb], ql[kk], Bh);
            }
        }

        // ---- factored softmax weights, tf32-quantized (self-consistent l) ----
        float p[2][4];
        #pragma unroll
        for (int nb = 0; nb < 2; nb++) {
            const int cj = ch + 8 * nb + 2 * tig;
            float f2a = f2s[cj], f2b = f2s[cj + 1];
            float ua = us[cj], ub = us[cj + 1];
            float wa = ws[cj], wb = ws[cj + 1];
            float p00 = (sacc[nb][0] > 0.f) ? ((f2a > t0) ? ua : rr0 * wa) : 0.f;
            float p01 = (sacc[nb][1] > 0.f) ? ((f2b > t0) ? ub : rr0 * wb) : 0.f;
            float p10 = (sacc[nb][2] > 0.f) ? ((f2a > t1) ? ua : rr1 * wa) : 0.f;
            float p11 = (sacc[nb][3] > 0.f) ? ((f2b > t1) ? ub : rr1 * wb) : 0.f;
            p00 = tf32round(p00); p01 = tf32round(p01);
            p10 = tf32round(p10); p11 = tf32round(p11);
            l0 += p00 + p01;
            l1 += p10 + p11;
            p[nb][0] = p00; p[nb][1] = p01; p[nb][2] = p10; p[nb][3] = p11;
        }

        // ---- C->A fragment conversion via shuffles, then PV (2 mma) ----
        // Value at (row, local col c) lives in lane 4*gid + ((c&7)>>1),
        // register p[c>>3][(c&1) + 2*(row==r1)].
        #pragma unroll
        for (int kk = 0; kk < 2; kk++) {
            const int srcA = 4 * gid + (tig >> 1);
            const int srcB = srcA + 2;
            float v0a = __shfl_sync(0xffffffffu, p[kk][0], srcA);
            float v0b = __shfl_sync(0xffffffffu, p[kk][1], srcA);
            float v1a = __shfl_sync(0xffffffffu, p[kk][2], srcA);
            float v1b = __shfl_sync(0xffffffffu, p[kk][3], srcA);
            float v2a = __shfl_sync(0xffffffffu, p[kk][0], srcB);
            float v2b = __shfl_sync(0xffffffffu, p[kk][1], srcB);
            float v3a = __shfl_sync(0xffffffffu, p[kk][2], srcB);
            float v3b = __shfl_sync(0xffffffffu, p[kk][3], srcB);
            const bool odd = (tig & 1);
            uint32_t Ah[4];
            Ah[0] = FU(odd ? v0b : v0a);   // (r0, 8kk+tig)
            Ah[1] = FU(odd ? v1b : v1a);   // (r1, 8kk+tig)
            Ah[2] = FU(odd ? v2b : v2a);   // (r0, 8kk+tig+4)
            Ah[3] = FU(odd ? v3b : v3a);   // (r1, 8kk+tig+4)
            #pragma unroll
            for (int nb = 0; nb < 8; nb++) {
                const int dc = 8 * nb + gid;
                float2 b0 = *(const float2*)&VTx[dc * TPV_ + 2 * (ch + 8 * kk + tig)];
                float2 b1 = *(const float2*)&VTx[dc * TPV_ + 2 * (ch + 8 * kk + tig + 4)];
                uint32_t Bh[2] = {FU(b0.x), FU(b1.x)};
                uint32_t Bl[2] = {FU(b0.y), FU(b1.y)};
                mma_tf32(oacc[nb], Ah, Bh);
                mma_tf32(oacc[nb], Ah, Bl);
            }
        }
    }

    // l: reduce within quad, combine across warps in smem
    l0 += __shfl_xor_sync(0xffffffffu, l0, 1);
    l0 += __shfl_xor_sync(0xffffffffu, l0, 2);
    l1 += __shfl_xor_sync(0xffffffffu, l1, 1);
    l1 += __shfl_xor_sync(0xffffffffu, l1, 2);
    if (tig == 0) {
        atomicAdd(&smf[SM_L + r0], l0);
        atomicAdd(&smf[SM_L + r1], l1);
    }
    __syncthreads();   // everyone out of the loop; VTx(0) now free as scratch

    // merge partial O across col-half warp pairs (w and w+4 share m-band)
    float* scratch = smf + SM_VTX(0);   // 64 rows x pitch 68 (fits in V buffer)
    if (w >= 4) {
        #pragma unroll
        for (int nb = 0; nb < 8; nb++) {
            const int dc = 8 * nb + 2 * tig;
            *(float2*)&scratch[r0 * 68 + dc] = make_float2(oacc[nb][0], oacc[nb][1]);
            *(float2*)&scratch[r1 * 68 + dc] = make_float2(oacc[nb][2], oacc[nb][3]);
        }
    }
    __syncthreads();

    const int rowb = (sp * H_ + h) * N_ + i0;
    if (tid < 64) g_pl[rowb + tid] = smf[SM_L + tid];

    if (w < 4) {
        #pragma unroll
        for (int nb = 0; nb < 8; nb++) {
            const int dc = 8 * nb + 2 * tig;
            float2 s0v = *(const float2*)&scratch[r0 * 68 + dc];
            float2 s1v = *(const float2*)&scratch[r1 * 68 + dc];
            *(float2*)&g_po[(size_t)(rowb + r0) * D_ + dc] =
                make_float2(oacc[nb][0] + s0v.x, oacc[nb][1] + s0v.y);
            *(float2*)&g_po[(size_t)(rowb + r1) * D_ + dc] =
                make_float2(oacc[nb][2] + s1v.x, oacc[nb][3] + s1v.y);
        }
    }
}

// ---------------------------------------------------------------------------
// K4b: merge the two KV splits, normalize, elu.  One thread per (h,n,d4).
// ---------------------------------------------------------------------------
__global__ void merge_kernel() {
    int idx = blockIdx.x * 256 + threadIdx.x;     // < H*N*16
    int d4 = (idx & 15) * 4;
    int hn = idx >> 4;
    float inv = 1.f / (g_pl[hn] + g_pl[HN_ + hn]);
    float4 o1 = *(const float4*)&g_po[(size_t)hn * D_ + d4];
    float4 o2 = *(const float4*)&g_po[(size_t)(HN_ + hn) * D_ + d4];
    float4 v;
    v.x = (o1.x + o2.x) * inv;
    v.y = (o1.y + o2.y) * inv;
    v.z = (o1.z + o2.z) * inv;
    v.w = (o1.w + o2.w) * inv;
    v.x = (v.x > 0.f) ? v.x : (__expf(v.x) - 1.f);
    v.y = (v.y > 0.f) ? v.y : (__expf(v.y) - 1.f);
    v.z = (v.z > 0.f) ? v.z : (__expf(v.z) - 1.f);
    v.w = (v.w > 0.f) ? v.w : (__expf(v.w) - 1.f);
    *(float4*)&g_head[(size_t)hn * D_ + d4] = v;
}

// ---------------------------------------------------------------------------
// K5: out = leaky( cat(heads) @ Wd + bd ).  Grid N/64, 256 threads.
// ---------------------------------------------------------------------------
__global__ void final_kernel(const float* __restrict__ Wd,
                             const float* __restrict__ bd,
                             float* __restrict__ out) {
    __shared__ float AT[64][68];
    __shared__ float Ws[64][64];
    const int n0 = blockIdx.x * 64;
    const int tid = threadIdx.x;
    const int ty = tid >> 4, tx = tid & 15;

    float acc[4][4] = {};

    for (int h = 0; h < H_; h++) {
        __syncthreads();
        for (int e = tid; e < 64 * 16; e += 256) {
            int r = e >> 4, k4 = (e & 15) * 4;
            float4 a = *(const float4*)&g_head[((size_t)h * N_ + n0 + r) * D_ + k4];
            AT[k4 + 0][r] = a.x;
            AT[k4 + 1][r] = a.y;
            AT[k4 + 2][r] = a.z;
            AT[k4 + 3][r] = a.w;
        }
        for (int e = tid; e < 64 * 16; e += 256) {
            int rr = e >> 4, c4 = (e & 15) * 4;
            *(float4*)&Ws[rr][c4] = *(const float4*)&Wd[(size_t)(h * 64 + rr) * D_ + c4];
        }
        __syncthreads();
        #pragma unroll 8
        for (int k = 0; k < 64; k++) {
            float4 a = *(float4*)&AT[k][4 * ty];
            float4 b = *(float4*)&Ws[k][4 * tx];
            acc[0][0] += a.x * b.x; acc[0][1] += a.x * b.y; acc[0][2] += a.x * b.z; acc[0][3] += a.x * b.w;
            acc[1][0] += a.y * b.x; acc[1][1] += a.y * b.y; acc[1][2] += a.y * b.z; acc[1][3] += a.y * b.w;
            acc[2][0] += a.z * b.x; acc[2][1] += a.z * b.y; acc[2][2] += a.z * b.z; acc[2][3] += a.z * b.w;
            acc[3][0] += a.w * b.x; acc[3][1] += a.w * b.y; acc[3][2] += a.w * b.z; acc[3][3] += a.w * b.w;
        }
    }
    #pragma unroll
    for (int j = 0; j < 4; j++) {
        float b = bd[4 * tx + j];
        #pragma unroll
        for (int i = 0; i < 4; i++) {
            float v = acc[i][j] + b;
            v = (v > 0.f) ? v : SLOPE_ * v;
            out[(size_t)(n0 + 4 * ty + i) * D_ + 4 * tx + j] = v;
        }
    }
}

// ---------------------------------------------------------------------------
extern "C" void kernel_launch(void* const* d_in, const int* in_sizes, int n_in,
                              void* d_out, int out_size) {
    const float* x    = (const float*)d_in[0];
    const float* mask = (const float*)d_in[1];
    const float* adj  = (const float*)d_in[2];
    const float* W    = (const float*)d_in[3];
    const float* a1   = (const float*)d_in[4];
    const float* a2   = (const float*)d_in[5];
    const float* aw   = (const float*)d_in[6];
    const float* Wd   = (const float*)d_in[7];
    const float* bd   = (const float*)d_in[8];
    float* out        = (float*)d_out;

    cudaFuncSetAttribute(flash_kernel,
                         cudaFuncAttributeMaxDynamicSharedMemorySize,
                         SM_FLOATS * (int)sizeof(float));

    wh_kernel<<<dim3(N_ / 64, H_), 256>>>(x, mask, W);
    f12_kernel<<<(H_ * N_) / 8, 256>>>(a1, a2);
    adjp_kernel<<<(N_ * M_) / 8, 256>>>(adj, aw);
    flash_kernel<<<dim3(N_ / 64, H_, 2), 256, SM_FLOATS * (int)sizeof(float)>>>();
    merge_kernel<<<(HN_ * 16) / 256, 256>>>();
    final_kernel<<<N_ / 64, 256>>>(Wd, bd, out);
}

// round 17
// speedup vs baseline: 1.4899x; 1.0001x over previous
#include <cuda_runtime.h>
#include <cstdint>

// ---------------------------------------------------------------------------
// GraphAttentionWithMask: 4-head GAT, N=4096, F=512, D=64, E=128, M=64
//
//  K1 wh_kernel    : Wh = (mask*x) @ W[h]; writes Wh, WhTx (tf32 hi/lo),
//                    AND f1/f2/u/w (fused f12) via half-warp reduce
//  K3 adjp_kernel  : adjpx[h][n][2m] = tf32 hi/lo of adj[n][m]·aw[h]
//  K4 flash_kernel : masked attention, factored softmax, tf32-quantized P.
//                    Warp-private j-halves, ONE barrier/tile.  S via 3xTF32
//                    with 3 INDEPENDENT accumulator chains (hh/hl/lh),
//                    PV 2-mma.  cp.async double buffer, 71 KB smem,
//                    2 CTAs/SM, split-KV x2.
//  K4b merge_kernel: (o1+o2)/(l1+l2), elu
//  K5 final_kernel : out = leaky(cat(heads) @ Wd + bd)
// ---------------------------------------------------------------------------

#define N_  4096
#define F_  512
#define D_  64
#define H_  4
#define E_  128
#define M_  64
#define HN_ (H_ * N_)
#define SLOPE_ 0.2f

__device__ __forceinline__ float2 tf32split(float a) {
    uint32_t hb;
    asm("cvt.rna.tf32.f32 %0, %1;" : "=r"(hb) : "f"(a));
    float hf = __uint_as_float(hb);
    return make_float2(hf, a - hf);
}

__device__ __forceinline__ float tf32round(float a) {
    uint32_t hb;
    asm("cvt.rna.tf32.f32 %0, %1;" : "=r"(hb) : "f"(a));
    return __uint_as_float(hb);
}

__device__ __forceinline__ void mma_tf32(float* d, const uint32_t* a, const uint32_t* b) {
    asm volatile(
        "mma.sync.aligned.m16n8k8.row.col.f32.tf32.tf32.f32 "
        "{%0,%1,%2,%3}, {%4,%5,%6,%7}, {%8,%9}, {%0,%1,%2,%3};"
        : "+f"(d[0]), "+f"(d[1]), "+f"(d[2]), "+f"(d[3])
        : "r"(a[0]), "r"(a[1]), "r"(a[2]), "r"(a[3]), "r"(b[0]), "r"(b[1]));
}

#define FU(x) __float_as_uint(x)

#define CP_ASYNC16(smaddr, gptr) \
    asm volatile("cp.async.cg.shared.global [%0], [%1], 16;" \
                 :: "r"(smaddr), "l"(gptr))
#define CP_COMMIT() asm volatile("cp.async.commit_group;")
#define CP_WAIT0()  asm volatile("cp.async.wait_group 0;")

__device__ float g_Wh   [H_ * N_ * D_];
__device__ float g_WhTx [H_ * D_ * 2 * N_];   // [h][d][2n] interleaved hi/lo
__device__ float g_adjpx[H_ * N_ * 2 * M_];   // [h][n][2m] interleaved hi/lo
__device__ float g_f1   [H_ * N_];
__device__ float g_f2   [H_ * N_];
__device__ float g_u    [H_ * N_];            // exp(f2)
__device__ float g_w    [H_ * N_];            // exp(0.2 f2)
__device__ float g_head [H_ * N_ * D_];
__device__ float g_po   [2 * H_ * N_ * D_];   // split-KV partials
__device__ float g_pl   [2 * H_ * N_];

// ---------------------------------------------------------------------------
// K1: Wh = (mask*x) @ W[h] + fused f1/f2/u/w.  Grid (N/64, H), 256 threads.
// ---------------------------------------------------------------------------
__global__ void wh_kernel(const float* __restrict__ x,
                          const float* __restrict__ mask,
                          const float* __restrict__ W,
                          const float* __restrict__ a1,
                          const float* __restrict__ a2) {
    __shared__ float xT[64][68];
    __shared__ float Ws[64][64];
    const int h  = blockIdx.y;
    const int n0 = blockIdx.x * 64;
    const int tid = threadIdx.x;
    const int ty = tid >> 4, tx = tid & 15;

    float acc[4][4] = {};

    for (int f0 = 0; f0 < F_; f0 += 64) {
        __syncthreads();
        for (int e = tid; e < 64 * 16; e += 256) {
            int r = e >> 4, k4 = (e & 15) * 4;
            float mk = mask[n0 + r];
            float4 xv = *(const float4*)&x[(size_t)(n0 + r) * F_ + f0 + k4];
            xT[k4 + 0][r] = xv.x * mk;
            xT[k4 + 1][r] = xv.y * mk;
            xT[k4 + 2][r] = xv.z * mk;
            xT[k4 + 3][r] = xv.w * mk;
        }
        for (int e = tid; e < 64 * 16; e += 256) {
            int rr = e >> 4, c4 = (e & 15) * 4;
            *(float4*)&Ws[rr][c4] =
                *(const float4*)&W[((size_t)h * F_ + f0 + rr) * D_ + c4];
        }
        __syncthreads();
        #pragma unroll 8
        for (int k = 0; k < 64; k++) {
            float4 a = *(float4*)&xT[k][4 * ty];
            float4 b = *(float4*)&Ws[k][4 * tx];
            acc[0][0] += a.x * b.x; acc[0][1] += a.x * b.y; acc[0][2] += a.x * b.z; acc[0][3] += a.x * b.w;
            acc[1][0] += a.y * b.x; acc[1][1] += a.y * b.y; acc[1][2] += a.y * b.z; acc[1][3] += a.y * b.w;
            acc[2][0] += a.z * b.x; acc[2][1] += a.z * b.y; acc[2][2] += a.z * b.z; acc[2][3] += a.z * b.w;
            acc[3][0] += a.w * b.x; acc[3][1] += a.w * b.y; acc[3][2] += a.w * b.z; acc[3][3] += a.w * b.w;
        }
    }
    #pragma unroll
    for (int i = 0; i < 4; i++)
        #pragma unroll
        for (int j = 0; j < 4; j++)
            g_Wh[((size_t)h * N_ + n0 + 4 * ty + i) * D_ + 4 * tx + j] = acc[i][j];
    // transposed hi/lo interleaved copy for flash PV mma (B operand)
    #pragma unroll
    for (int j = 0; j < 4; j++) {
        float2 s0 = tf32split(acc[0][j]);
        float2 s1 = tf32split(acc[1][j]);
        float2 s2 = tf32split(acc[2][j]);
        float2 s3 = tf32split(acc[3][j]);
        size_t base = ((size_t)h * D_ + 4 * tx + j) * (2 * N_) + 2 * (n0 + 4 * ty);
        *(float4*)&g_WhTx[base]     = make_float4(s0.x, s0.y, s1.x, s1.y);
        *(float4*)&g_WhTx[base + 4] = make_float4(s2.x, s2.y, s3.x, s3.y);
    }
    // fused f12: rows 4ty+i live across the 16 same-ty lanes (contiguous in warp)
    const float4 a1v = *(const float4*)&a1[h * D_ + 4 * tx];
    const float4 a2v = *(const float4*)&a2[h * D_ + 4 * tx];
    #pragma unroll
    for (int i = 0; i < 4; i++) {
        float s1 = acc[i][0] * a1v.x + acc[i][1] * a1v.y + acc[i][2] * a1v.z + acc[i][3] * a1v.w;
        float s2 = acc[i][0] * a2v.x + acc[i][1] * a2v.y + acc[i][2] * a2v.z + acc[i][3] * a2v.w;
        #pragma unroll
        for (int off = 8; off; off >>= 1) {
            s1 += __shfl_xor_sync(0xffffffffu, s1, off);
            s2 += __shfl_xor_sync(0xffffffffu, s2, off);
        }
        if (tx == 0) {
            int n = h * N_ + n0 + 4 * ty + i;
            g_f1[n] = s1;
            g_f2[n] = s2;
            g_u [n] = __expf(s2);
            g_w [n] = __expf(0.2f * s2);
        }
    }
}

// ---------------------------------------------------------------------------
// K3: adjpx[h][n][2m] = tf32 hi/lo of adj[n][m]·aw[h].  One warp per (n,m).
// ---------------------------------------------------------------------------
__global__ void adjp_kernel(const float* __restrict__ adj,
                            const float* __restrict__ aw) {
    __shared__ float aws[H_ * E_];
    int tid = threadIdx.x;
    if (tid < H_ * E_) aws[tid] = aw[tid];
    if (tid + 256 < H_ * E_) aws[tid + 256] = aw[tid + 256];
    __syncthreads();

    int w = (blockIdx.x * blockDim.x + tid) >> 5;   // 0..N*M-1
    int lane = tid & 31;
    int n = w / M_, m = w % M_;
    float4 v = ((const float4*)&adj[(size_t)(n * M_ + m) * E_])[lane];
    float s[H_];
    #pragma unroll
    for (int h = 0; h < H_; h++) {
        const float4 aw4 = ((const float4*)&aws[h * E_])[lane];
        s[h] = v.x * aw4.x + v.y * aw4.y + v.z * aw4.z + v.w * aw4.w;
    }
    #pragma unroll
    for (int off = 16; off; off >>= 1) {
        #pragma unroll
        for (int h = 0; h < H_; h++)
            s[h] += __shfl_xor_sync(0xffffffffu, s[h], off);
    }
    if (lane == 0) {
        #pragma unroll
        for (int h = 0; h < H_; h++) {
            float2 sp = tf32split(s[h]);
            *(float2*)&g_adjpx[((size_t)h * N_ + n) * (2 * M_) + 2 * m] = sp;
        }
    }
}

// ---------------------------------------------------------------------------
// K4: flash attention, warp-private j-halves, ONE barrier per tile.
// S phase uses 3 independent accumulator chains (hh / hl / lh).
// Grid (N/64, H, 2), 256 threads = 8 warps.
// ---------------------------------------------------------------------------
#define TPK_ 136   // K tile pitch: 32 rows x (2*64 + 8)
#define TPV_ 68    // V tile pitch: 64 rows x (2*32 + 4)
#define SM_KTX(b)  ((b) * 32 * TPK_)
#define SM_VTX(b)  (2 * 32 * TPK_ + (b) * 64 * TPV_)
#define SM_SCAL(b) (2 * 32 * TPK_ + 2 * 64 * TPV_ + (b) * 96)
#define SM_T       (2 * 32 * TPK_ + 2 * 64 * TPV_ + 192)
#define SM_R       (SM_T + 64)
#define SM_L       (SM_R + 64)
#define SM_FLOATS  (SM_L + 64)

__device__ __forceinline__ void prefetch_tile(float* smf, int b, int h, int j0, int tid) {
    uint32_t kbase = (uint32_t)__cvta_generic_to_shared(smf + SM_KTX(b));
    uint32_t vbase = (uint32_t)__cvta_generic_to_shared(smf + SM_VTX(b));
    #pragma unroll
    for (int e = tid; e < 32 * 32; e += 256) {   // K: 32 rows x 32 chunks
        int r = e >> 5, c4 = (e & 31) * 4;
        CP_ASYNC16(kbase + (uint32_t)(r * TPK_ + c4) * 4,
                   &g_adjpx[((size_t)h * N_ + j0 + r) * (2 * M_) + c4]);
    }
    #pragma unroll
    for (int e = tid; e < 64 * 16; e += 256) {   // V: 64 rows x 16 chunks
        int r = e >> 4, c4 = (e & 15) * 4;
        CP_ASYNC16(vbase + (uint32_t)(r * TPV_ + c4) * 4,
                   &g_WhTx[((size_t)h * D_ + r) * (2 * N_) + 2 * j0 + c4]);
    }
    if (tid < 8) {
        uint32_t sbase = (uint32_t)__cvta_generic_to_shared(smf + SM_SCAL(b));
        CP_ASYNC16(sbase + tid * 16,       &g_f2[h * N_ + j0 + tid * 4]);
        CP_ASYNC16(sbase + 128 + tid * 16, &g_u [h * N_ + j0 + tid * 4]);
        CP_ASYNC16(sbase + 256 + tid * 16, &g_w [h * N_ + j0 + tid * 4]);
    }
    CP_COMMIT();
}

__global__ void __launch_bounds__(256, 2) flash_kernel() {
    extern __shared__ float smf[];

    const int h  = blockIdx.y;
    const int i0 = blockIdx.x * 64;
    const int sp = blockIdx.z;
    const int tid = threadIdx.x;
    const int w = tid >> 5, lane = tid & 31;
    const int gid = lane >> 2, tig = lane & 3;
    const int mw = (w & 3) * 16;          // m-band
    const int ch = (w >> 2) * 16;         // j col-half (16 cols of each tile)
    const int r0 = mw + gid, r1 = r0 + 8;

    const int j0base = sp * 2048;
    prefetch_tile(smf, 0, h, j0base, tid);

    // Q fragments: registers, loaded once (reused for all 64 j-tiles)
    uint32_t qh[8][4], ql[8][4];
    {
        const size_t base0 = ((size_t)h * N_ + i0 + r0) * (2 * M_);
        const size_t base1 = ((size_t)h * N_ + i0 + r1) * (2 * M_);
        #pragma unroll
        for (int kk = 0; kk < 8; kk++) {
            float2 a0 = *(const float2*)&g_adjpx[base0 + 2 * (kk * 8 + tig)];
            float2 a1 = *(const float2*)&g_adjpx[base1 + 2 * (kk * 8 + tig)];
            float2 a2 = *(const float2*)&g_adjpx[base0 + 2 * (kk * 8 + tig + 4)];
            float2 a3 = *(const float2*)&g_adjpx[base1 + 2 * (kk * 8 + tig + 4)];
            qh[kk][0] = FU(a0.x); qh[kk][1] = FU(a1.x); qh[kk][2] = FU(a2.x); qh[kk][3] = FU(a3.x);
            ql[kk][0] = FU(a0.y); ql[kk][1] = FU(a1.y); ql[kk][2] = FU(a2.y); ql[kk][3] = FU(a3.y);
        }
    }
    if (tid < 64) {
        float f1v = g_f1[h * N_ + i0 + tid];
        smf[SM_T + tid] = -f1v;
        smf[SM_R + tid] = __expf(-0.8f * f1v);
        smf[SM_L + tid] = 0.f;
    }
    __syncthreads();
    const float t0 = smf[SM_T + r0], t1 = smf[SM_T + r1];
    const float rr0 = smf[SM_R + r0], rr1 = smf[SM_R + r1];

    float oacc[8][4] = {};     // all 64 dims (8 n-blocks), warp's j-half only
    float l0 = 0.f, l1 = 0.f;

    for (int it = 0; it < 64; it++) {
        const int b = it & 1;
        float* KTx = smf + SM_KTX(b);
        float* VTx = smf + SM_VTX(b);
        const float* f2s = smf + SM_SCAL(b);
        const float* us = f2s + 32;
        const float* ws = f2s + 64;

        CP_WAIT0();
        __syncthreads();   // buffer b landed for all; prev iter fully finished
        if (it < 63) prefetch_tile(smf, 1 - b, h, j0base + (it + 1) * 32, tid);

        // ---- S = Q @ K^T: 3 independent accumulator chains per nb ----
        float s_hh[2][4] = {}, s_hl[2][4] = {}, s_lh[2][4] = {};
        #pragma unroll
        for (int kk = 0; kk < 8; kk++) {
            const int k0 = kk * 8;
            #pragma unroll
            for (int nb = 0; nb < 2; nb++) {
                const int jc = ch + 8 * nb + gid;
                float2 b0 = *(const float2*)&KTx[jc * TPK_ + 2 * (k0 + tig)];
                float2 b1 = *(const float2*)&KTx[jc * TPK_ + 2 * (k0 + tig + 4)];
                uint32_t Bh[2] = {FU(b0.x), FU(b1.x)};
                uint32_t Bl[2] = {FU(b0.y), FU(b1.y)};
                mma_tf32(s_hh[nb], qh[kk], Bh);
                mma_tf32(s_hl[nb], qh[kk], Bl);
                mma_tf32(s_lh[nb], ql[kk], Bh);
            }
        }

        // ---- factored softmax weights, tf32-quantized (self-consistent l) ----
        float p[2][4];
        #pragma unroll
        for (int nb = 0; nb < 2; nb++) {
            const int cj = ch + 8 * nb + 2 * tig;
            float sv0 = s_hh[nb][0] + (s_hl[nb][0] + s_lh[nb][0]);
            float sv1 = s_hh[nb][1] + (s_hl[nb][1] + s_lh[nb][1]);
            float sv2 = s_hh[nb][2] + (s_hl[nb][2] + s_lh[nb][2]);
            float sv3 = s_hh[nb][3] + (s_hl[nb][3] + s_lh[nb][3]);
            float f2a = f2s[cj], f2b = f2s[cj + 1];
            float ua = us[cj], ub = us[cj + 1];
            float wa = ws[cj], wb = ws[cj + 1];
            float p00 = (sv0 > 0.f) ? ((f2a > t0) ? ua : rr0 * wa) : 0.f;
            float p01 = (sv1 > 0.f) ? ((f2b > t0) ? ub : rr0 * wb) : 0.f;
            float p10 = (sv2 > 0.f) ? ((f2a > t1) ? ua : rr1 * wa) : 0.f;
            float p11 = (sv3 > 0.f) ? ((f2b > t1) ? ub : rr1 * wb) : 0.f;
            p00 = tf32round(p00); p01 = tf32round(p01);
            p10 = tf32round(p10); p11 = tf32round(p11);
            l0 += p00 + p01;
            l1 += p10 + p11;
            p[nb][0] = p00; p[nb][1] = p01; p[nb][2] = p10; p[nb][3] = p11;
        }

        // ---- C->A fragment conversion via shuffles, then PV (2 mma) ----
        #pragma unroll
        for (int kk = 0; kk < 2; kk++) {
            const int srcA = 4 * gid + (tig >> 1);
            const int srcB = srcA + 2;
            float v0a = __shfl_sync(0xffffffffu, p[kk][0], srcA);
            float v0b = __shfl_sync(0xffffffffu, p[kk][1], srcA);
            float v1a = __shfl_sync(0xffffffffu, p[kk][2], srcA);
            float v1b = __shfl_sync(0xffffffffu, p[kk][3], srcA);
            float v2a = __shfl_sync(0xffffffffu, p[kk][0], srcB);
            float v2b = __shfl_sync(0xffffffffu, p[kk][1], srcB);
            float v3a = __shfl_sync(0xffffffffu, p[kk][2], srcB);
            float v3b = __shfl_sync(0xffffffffu, p[kk][3], srcB);
            const bool odd = (tig & 1);
            uint32_t Ah[4];
            Ah[0] = FU(odd ? v0b : v0a);   // (r0, 8kk+tig)
            Ah[1] = FU(odd ? v1b : v1a);   // (r1, 8kk+tig)
            Ah[2] = FU(odd ? v2b : v2a);   // (r0, 8kk+tig+4)
            Ah[3] = FU(odd ? v3b : v3a);   // (r1, 8kk+tig+4)
            #pragma unroll
            for (int nb = 0; nb < 8; nb++) {
                const int dc = 8 * nb + gid;
                float2 b0 = *(const float2*)&VTx[dc * TPV_ + 2 * (ch + 8 * kk + tig)];
                float2 b1 = *(const float2*)&VTx[dc * TPV_ + 2 * (ch + 8 * kk + tig + 4)];
                uint32_t Bh[2] = {FU(b0.x), FU(b1.x)};
                uint32_t Bl[2] = {FU(b0.y), FU(b1.y)};
                mma_tf32(oacc[nb], Ah, Bh);
                mma_tf32(oacc[nb], Ah, Bl);
            }
        }
    }

    // l: reduce within quad, combine across warps in smem
    l0 += __shfl_xor_sync(0xffffffffu, l0, 1);
    l0 += __shfl_xor_sync(0xffffffffu, l0, 2);
    l1 += __shfl_xor_sync(0xffffffffu, l1, 1);
    l1 += __shfl_xor_sync(0xffffffffu, l1, 2);
    if (tig == 0) {
        atomicAdd(&smf[SM_L + r0], l0);
        atomicAdd(&smf[SM_L + r1], l1);
    }
    __syncthreads();   // everyone out of the loop; VTx(0) now free as scratch

    // merge partial O across col-half warp pairs (w and w+4 share m-band)
    float* scratch = smf + SM_VTX(0);   // 64 rows x pitch 68 (fits in V buffer)
    if (w >= 4) {
        #pragma unroll
        for (int nb = 0; nb < 8; nb++) {
            const int dc = 8 * nb + 2 * tig;
            *(float2*)&scratch[r0 * 68 + dc] = make_float2(oacc[nb][0], oacc[nb][1]);
            *(float2*)&scratch[r1 * 68 + dc] = make_float2(oacc[nb][2], oacc[nb][3]);
        }
    }
    __syncthreads();

    const int rowb = (sp * H_ + h) * N_ + i0;
    if (tid < 64) g_pl[rowb + tid] = smf[SM_L + tid];

    if (w < 4) {
        #pragma unroll
        for (int nb = 0; nb < 8; nb++) {
            const int dc = 8 * nb + 2 * tig;
            float2 s0v = *(const float2*)&scratch[r0 * 68 + dc];
            float2 s1v = *(const float2*)&scratch[r1 * 68 + dc];
            *(float2*)&g_po[(size_t)(rowb + r0) * D_ + dc] =
                make_float2(oacc[nb][0] + s0v.x, oacc[nb][1] + s0v.y);
            *(float2*)&g_po[(size_t)(rowb + r1) * D_ + dc] =
                make_float2(oacc[nb][2] + s1v.x, oacc[nb][3] + s1v.y);
        }
    }
}

// ---------------------------------------------------------------------------
// K4b: merge the two KV splits, normalize, elu.  One thread per (h,n,d4).
// ---------------------------------------------------------------------------
__global__ void merge_kernel() {
    int idx = blockIdx.x * 256 + threadIdx.x;     // < H*N*16
    int d4 = (idx & 15) * 4;
    int hn = idx >> 4;
    float inv = 1.f / (g_pl[hn] + g_pl[HN_ + hn]);
    float4 o1 = *(const float4*)&g_po[(size_t)hn * D_ + d4];
    float4 o2 = *(const float4*)&g_po[(size_t)(HN_ + hn) * D_ + d4];
    float4 v;
    v.x = (o1.x + o2.x) * inv;
    v.y = (o1.y + o2.y) * inv;
    v.z = (o1.z + o2.z) * inv;
    v.w = (o1.w + o2.w) * inv;
    v.x = (v.x > 0.f) ? v.x : (__expf(v.x) - 1.f);
    v.y = (v.y > 0.f) ? v.y : (__expf(v.y) - 1.f);
    v.z = (v.z > 0.f) ? v.z : (__expf(v.z) - 1.f);
    v.w = (v.w > 0.f) ? v.w : (__expf(v.w) - 1.f);
    *(float4*)&g_head[(size_t)hn * D_ + d4] = v;
}

// ---------------------------------------------------------------------------
// K5: out = leaky( cat(heads) @ Wd + bd ).  Grid N/64, 256 threads.
// ---------------------------------------------------------------------------
__global__ void final_kernel(const float* __restrict__ Wd,
                             const float* __restrict__ bd,
                             float* __restrict__ out) {
    __shared__ float AT[64][68];
    __shared__ float Ws[64][64];
    const int n0 = blockIdx.x * 64;
    const int tid = threadIdx.x;
    const int ty = tid >> 4, tx = tid & 15;

    float acc[4][4] = {};

    for (int h = 0; h < H_; h++) {
        __syncthreads();
        for (int e = tid; e < 64 * 16; e += 256) {
            int r = e >> 4, k4 = (e & 15) * 4;
            float4 a = *(const float4*)&g_head[((size_t)h * N_ + n0 + r) * D_ + k4];
            AT[k4 + 0][r] = a.x;
            AT[k4 + 1][r] = a.y;
            AT[k4 + 2][r] = a.z;
            AT[k4 + 3][r] = a.w;
        }
        for (int e = tid; e < 64 * 16; e += 256) {
            int rr = e >> 4, c4 = (e & 15) * 4;
            *(float4*)&Ws[rr][c4] = *(const float4*)&Wd[(size_t)(h * 64 + rr) * D_ + c4];
        }
        __syncthreads();
        #pragma unroll 8
        for (int k = 0; k < 64; k++) {
            float4 a = *(float4*)&AT[k][4 * ty];
            float4 b = *(float4*)&Ws[k][4 * tx];
            acc[0][0] += a.x * b.x; acc[0][1] += a.x * b.y; acc[0][2] += a.x * b.z; acc[0][3] += a.x * b.w;
            acc[1][0] += a.y * b.x; acc[1][1] += a.y * b.y; acc[1][2] += a.y * b.z; acc[1][3] += a.y * b.w;
            acc[2][0] += a.z * b.x; acc[2][1] += a.z * b.y; acc[2][2] += a.z * b.z; acc[2][3] += a.z * b.w;
            acc[3][0] += a.w * b.x; acc[3][1] += a.w * b.y; acc[3][2] += a.w * b.z; acc[3][3] += a.w * b.w;
        }
    }
    #pragma unroll
    for (int j = 0; j < 4; j++) {
        float b = bd[4 * tx + j];
        #pragma unroll
        for (int i = 0; i < 4; i++) {
            float v = acc[i][j] + b;
            v = (v > 0.f) ? v : SLOPE_ * v;
            out[(size_t)(n0 + 4 * ty + i) * D_ + 4 * tx + j] = v;
        }
    }
}

// ---------------------------------------------------------------------------
extern "C" void kernel_launch(void* const* d_in, const int* in_sizes, int n_in,
                              void* d_out, int out_size) {
    const float* x    = (const float*)d_in[0];
    const float* mask = (const float*)d_in[1];
    const float* adj  = (const float*)d_in[2];
    const float* W    = (const float*)d_in[3];
    const float* a1   = (const float*)d_in[4];
    const float* a2   = (const float*)d_in[5];
    const float* aw   = (const float*)d_in[6];
    const float* Wd   = (const float*)d_in[7];
    const float* bd   = (const float*)d_in[8];
    float* out        = (float*)d_out;

    cudaFuncSetAttribute(flash_kernel,
                         cudaFuncAttributeMaxDynamicSharedMemorySize,
                         SM_FLOATS * (int)sizeof(float));

    wh_kernel<<<dim3(N_ / 64, H_), 256>>>(x, mask, W, a1, a2);
    adjp_kernel<<<(N_ * M_) / 8, 256>>>(adj, aw);
    flash_kernel<<<dim3(N_ / 64, H_, 2), 256, SM_FLOATS * (int)sizeof(float)>>>();
    merge_kernel<<<(HN_ * 16) / 256, 256>>>();
    final_kernel<<<N_ / 64, 256>>>(Wd, bd, out);
}